// round 1
// baseline (speedup 1.0000x reference)
#include <cuda_runtime.h>
#include <cuda_bf16.h>

#define NN 50000
#define EE 850000
#define DIM 256

// ---------------- scratch (device globals; no allocation allowed) -------------
__device__ float    g_hp[NN * DIM];       // projected features (reused by both layers)
__device__ float    g_h [NN * DIM];       // layer-1 output (post relu)
__device__ float    g_ssrc[NN * 4];
__device__ float    g_sdst[NN * 4];
__device__ unsigned g_key [NN * 4];       // segment-max keys
__device__ float    g_emax[NN * 4];
__device__ float    g_esum[NN * 4];
__device__ float    g_e   [EE * 4];       // per-edge logits -> exp values

// ---------------- GEMM: C[n][m] = sum_k A[n][k] * B[m][k], K=M=256 ------------
__global__ void gemm_nt64(const float* __restrict__ A, const float* __restrict__ B,
                          float* __restrict__ C, int N) {
    const int K = DIM;
    __shared__ float As[16][64];
    __shared__ float Bs[16][64];
    int tid = threadIdx.x;         // 256 threads
    int tx = tid & 15, ty = tid >> 4;
    int n0 = blockIdx.x * 64;
    int m0 = blockIdx.y * 64;

    float acc[4][4];
#pragma unroll
    for (int i = 0; i < 4; i++)
#pragma unroll
        for (int j = 0; j < 4; j++) acc[i][j] = 0.f;

    int lr = tid >> 2;             // 0..63 tile row
    int lk = (tid & 3) * 4;        // 0,4,8,12 k offset

    for (int k0 = 0; k0 < K; k0 += 16) {
        int an = n0 + lr;
        float4 av = (an < N) ? *(const float4*)(A + (size_t)an * K + k0 + lk)
                             : make_float4(0.f, 0.f, 0.f, 0.f);
        As[lk + 0][lr] = av.x; As[lk + 1][lr] = av.y;
        As[lk + 2][lr] = av.z; As[lk + 3][lr] = av.w;
        float4 bv = *(const float4*)(B + (size_t)(m0 + lr) * K + k0 + lk);
        Bs[lk + 0][lr] = bv.x; Bs[lk + 1][lr] = bv.y;
        Bs[lk + 2][lr] = bv.z; Bs[lk + 3][lr] = bv.w;
        __syncthreads();
#pragma unroll
        for (int k = 0; k < 16; k++) {
            float a[4], b[4];
#pragma unroll
            for (int i = 0; i < 4; i++) a[i] = As[k][ty * 4 + i];
#pragma unroll
            for (int j = 0; j < 4; j++) b[j] = Bs[k][tx * 4 + j];
#pragma unroll
            for (int i = 0; i < 4; i++)
#pragma unroll
                for (int j = 0; j < 4; j++) acc[i][j] = fmaf(a[i], b[j], acc[i][j]);
        }
        __syncthreads();
    }
#pragma unroll
    for (int i = 0; i < 4; i++) {
        int n = n0 + ty * 4 + i;
        if (n < N) {
            float4 o = make_float4(acc[i][0], acc[i][1], acc[i][2], acc[i][3]);
            *(float4*)(C + (size_t)n * DIM + m0 + tx * 4) = o;
        }
    }
}

// --------------- per-node attention scores: s[n][h] = dot(hp[n,h,:], a[h,:]) ---
// a_src/a_dst flattened to length 256 (H*F). One block (256 thr) per node.
__global__ void node_scores(const float* __restrict__ hp,
                            const float* __restrict__ a_src,
                            const float* __restrict__ a_dst,
                            float* __restrict__ s_src, float* __restrict__ s_dst,
                            int Hh, int F) {
    int n = blockIdx.x;
    int t = threadIdx.x;
    float v = hp[(size_t)n * DIM + t];
    __shared__ float shs[DIM];
    __shared__ float shd[DIM];
    shs[t] = v * a_src[t];
    shd[t] = v * a_dst[t];
    __syncthreads();
    for (int st = F >> 1; st > 0; st >>= 1) {
        if ((t & (F - 1)) < st) { shs[t] += shs[t + st]; shd[t] += shd[t + st]; }
        __syncthreads();
    }
    if ((t & (F - 1)) == 0) {
        int h = t / F;
        s_src[(size_t)n * Hh + h] = shs[t];
        s_dst[(size_t)n * Hh + h] = shd[t];
    }
}

// --------------- edge logits + leaky relu + segment-max (order-preserving key) -
__global__ void edge_logits(const int* __restrict__ src, const int* __restrict__ dst,
                            const float* __restrict__ s_src, const float* __restrict__ s_dst,
                            float* __restrict__ e, unsigned* __restrict__ keymax,
                            int E, int Hh) {
    int i = blockIdx.x * blockDim.x + threadIdx.x;
    if (i >= E * Hh) return;
    int eid = i / Hh;
    int h   = i - eid * Hh;
    int s = src[eid], d = dst[eid];
    float v = s_src[(size_t)s * Hh + h] + s_dst[(size_t)d * Hh + h];
    v = v > 0.f ? v : 0.2f * v;   // leaky relu
    e[i] = v;
    unsigned b = __float_as_uint(v);
    unsigned key = (b & 0x80000000u) ? ~b : (b | 0x80000000u);
    atomicMax(&keymax[(size_t)d * Hh + h], key);
}

__global__ void key_to_max(const unsigned* __restrict__ key, float* __restrict__ emax, int n) {
    int i = blockIdx.x * blockDim.x + threadIdx.x;
    if (i >= n) return;
    unsigned k = key[i];
    unsigned b = (k & 0x80000000u) ? (k ^ 0x80000000u) : ~k;
    emax[i] = __uint_as_float(b);
}

// --------------- exp(e - max) + segment-sum -----------------------------------
__global__ void edge_exp(const int* __restrict__ dst,
                         float* __restrict__ e, const float* __restrict__ emax,
                         float* __restrict__ esum, int E, int Hh) {
    int i = blockIdx.x * blockDim.x + threadIdx.x;
    if (i >= E * Hh) return;
    int eid = i / Hh;
    int h   = i - eid * Hh;
    int d = dst[eid];
    float ex = __expf(e[i] - emax[(size_t)d * Hh + h]);
    e[i] = ex;
    atomicAdd(&esum[(size_t)d * Hh + h], ex);
}

// --------------- aggregation: out[dst] += hp[src] * alpha ---------------------
// 64 threads per edge, float4 each; 4 edges per 256-thread block.
__global__ void aggregate(const int* __restrict__ src, const int* __restrict__ dst,
                          const float* __restrict__ hp, const float* __restrict__ ex,
                          const float* __restrict__ esum, float* __restrict__ out,
                          int E, int Hh) {
    int lane64 = threadIdx.x & 63;
    int esub   = threadIdx.x >> 6;
    int eid = blockIdx.x * 4 + esub;
    if (eid >= E) return;
    int s = src[eid], d = dst[eid];
    int h = (lane64 * Hh) >> 6;   // head of this float4 (F is 64 or 256)
    float alpha = ex[(size_t)eid * Hh + h] / (esum[(size_t)d * Hh + h] + 1e-16f);
    float4 v = *(const float4*)(hp + (size_t)s * DIM + lane64 * 4);
    v.x *= alpha; v.y *= alpha; v.z *= alpha; v.w *= alpha;
    float* addr = out + (size_t)d * DIM + lane64 * 4;
    asm volatile("red.global.add.v4.f32 [%0], {%1, %2, %3, %4};"
                 :: "l"(addr), "f"(v.x), "f"(v.y), "f"(v.z), "f"(v.w)
                 : "memory");
}

__global__ void relu_inplace(float* __restrict__ p, int n4) {
    int i = blockIdx.x * blockDim.x + threadIdx.x;
    if (i >= n4) return;
    float4 v = ((float4*)p)[i];
    v.x = fmaxf(v.x, 0.f); v.y = fmaxf(v.y, 0.f);
    v.z = fmaxf(v.z, 0.f); v.w = fmaxf(v.w, 0.f);
    ((float4*)p)[i] = v;
}

// ------------------------------------------------------------------------------
extern "C" void kernel_launch(void* const* d_in, const int* in_sizes, int n_in,
                              void* d_out, int out_size) {
    const float* x      = (const float*)d_in[0];
    const int*   ei     = (const int*)  d_in[1];
    const float* W1     = (const float*)d_in[2];
    const float* a1_src = (const float*)d_in[3];
    const float* a1_dst = (const float*)d_in[4];
    const float* W2     = (const float*)d_in[5];
    const float* a2_src = (const float*)d_in[6];
    const float* a2_dst = (const float*)d_in[7];

    int N = in_sizes[0] / DIM;
    int E = in_sizes[1] / 2;
    const int* src = ei;
    const int* dst = ei + E;

    float *hp, *h, *ssrc, *sdst, *emax, *esum, *ebuf;
    unsigned* key;
    cudaGetSymbolAddress((void**)&hp,   g_hp);
    cudaGetSymbolAddress((void**)&h,    g_h);
    cudaGetSymbolAddress((void**)&ssrc, g_ssrc);
    cudaGetSymbolAddress((void**)&sdst, g_sdst);
    cudaGetSymbolAddress((void**)&key,  g_key);
    cudaGetSymbolAddress((void**)&emax, g_emax);
    cudaGetSymbolAddress((void**)&esum, g_esum);
    cudaGetSymbolAddress((void**)&ebuf, g_e);

    float* out = (float*)d_out;

    dim3 gemm_grid((N + 63) / 64, DIM / 64);

    // ================= layer 1 (H=4, F=64) =================
    const int H1 = 4;
    cudaMemsetAsync(key,  0, (size_t)N * H1 * sizeof(unsigned));
    cudaMemsetAsync(esum, 0, (size_t)N * H1 * sizeof(float));
    cudaMemsetAsync(h,    0, (size_t)N * DIM * sizeof(float));

    gemm_nt64<<<gemm_grid, 256>>>(x, W1, hp, N);
    node_scores<<<N, 256>>>(hp, a1_src, a1_dst, ssrc, sdst, H1, DIM / H1);
    edge_logits<<<(E * H1 + 255) / 256, 256>>>(src, dst, ssrc, sdst, ebuf, key, E, H1);
    key_to_max<<<(N * H1 + 255) / 256, 256>>>(key, emax, N * H1);
    edge_exp<<<(E * H1 + 255) / 256, 256>>>(dst, ebuf, emax, esum, E, H1);
    aggregate<<<(E + 3) / 4, 256>>>(src, dst, hp, ebuf, esum, h, E, H1);
    relu_inplace<<<(N * DIM / 4 + 255) / 256, 256>>>(h, N * DIM / 4);

    // ================= layer 2 (H=1, F=256) =================
    const int H2 = 1;
    cudaMemsetAsync(key,  0, (size_t)N * H2 * sizeof(unsigned));
    cudaMemsetAsync(esum, 0, (size_t)N * H2 * sizeof(float));
    cudaMemsetAsync(out,  0, (size_t)N * DIM * sizeof(float));

    gemm_nt64<<<gemm_grid, 256>>>(h, W2, hp, N);
    node_scores<<<N, 256>>>(hp, a2_src, a2_dst, ssrc, sdst, H2, DIM / H2);
    edge_logits<<<(E * H2 + 255) / 256, 256>>>(src, dst, ssrc, sdst, ebuf, key, E, H2);
    key_to_max<<<(N * H2 + 255) / 256, 256>>>(key, emax, N * H2);
    edge_exp<<<(E * H2 + 255) / 256, 256>>>(dst, ebuf, emax, esum, E, H2);
    aggregate<<<(E + 3) / 4, 256>>>(src, dst, hp, ebuf, esum, out, E, H2);
    // H2=1 -> mean over heads is identity; out is final.
}

// round 2
// speedup vs baseline: 1.1288x; 1.1288x over previous
#include <cuda_runtime.h>
#include <cuda_bf16.h>

#define NN 50000
#define EE 850000
#define DIM 256

// ---------------- scratch (device globals; no allocation allowed) -------------
__device__ float g_hp[NN * DIM];       // projected features (reused by both layers)
__device__ float g_h [NN * DIM];       // layer-1 output (post relu)
__device__ float g_ssrc[NN * 4];
__device__ float g_sdst[NN * 4];
__device__ int   g_cnt   [NN];
__device__ int   g_rowptr[NN + 1];
__device__ int   g_cursor[NN];
__device__ int   g_srcs  [EE];         // edge src ids, grouped by dst (CSR)

// =================== GEMM: C[n][m] = sum_k A[n][k]*B[m][k], K=M=256 ===========
// 128x128 tile, 256 threads, 8x8 per thread, packed f32x2 FMA (FFMA2).
__global__ __launch_bounds__(256) void gemm_f32x2(const float* __restrict__ A,
                                                  const float* __restrict__ B,
                                                  float* __restrict__ C, int N) {
    __shared__ float As[16][128];
    __shared__ float Bs[16][128];
    int tid = threadIdx.x;
    int tx = tid & 15;       // column group
    int ty = tid >> 4;       // row group
    int n0 = blockIdx.x * 128;
    int m0 = blockIdx.y * 128;

    unsigned long long acc[8][4];
#pragma unroll
    for (int i = 0; i < 8; i++)
#pragma unroll
        for (int j = 0; j < 4; j++) acc[i][j] = 0ull;

    int lrow = tid >> 1;          // 0..127
    int lkq  = (tid & 1) * 8;     // k element offset 0 or 8

    for (int k0 = 0; k0 < 256; k0 += 16) {
#pragma unroll
        for (int q = 0; q < 2; q++) {
            int kk = lkq + q * 4;
            float4 av = make_float4(0.f, 0.f, 0.f, 0.f);
            if (n0 + lrow < N)
                av = *(const float4*)(A + (size_t)(n0 + lrow) * 256 + k0 + kk);
            As[kk + 0][lrow] = av.x; As[kk + 1][lrow] = av.y;
            As[kk + 2][lrow] = av.z; As[kk + 3][lrow] = av.w;
            float4 bv = *(const float4*)(B + (size_t)(m0 + lrow) * 256 + k0 + kk);
            Bs[kk + 0][lrow] = bv.x; Bs[kk + 1][lrow] = bv.y;
            Bs[kk + 2][lrow] = bv.z; Bs[kk + 3][lrow] = bv.w;
        }
        __syncthreads();
#pragma unroll
        for (int k = 0; k < 16; k++) {
            unsigned long long b[4];
#pragma unroll
            for (int jj = 0; jj < 4; jj++)
                b[jj] = *(const unsigned long long*)&Bs[k][tx * 2 + 32 * jj];
#pragma unroll
            for (int ii = 0; ii < 4; ii++) {
                float a0 = As[k][ty * 2 + 32 * ii];
                float a1 = As[k][ty * 2 + 32 * ii + 1];
                unsigned long long a0p, a1p;
                asm("mov.b64 %0, {%1, %1};" : "=l"(a0p) : "f"(a0));
                asm("mov.b64 %0, {%1, %1};" : "=l"(a1p) : "f"(a1));
#pragma unroll
                for (int jj = 0; jj < 4; jj++) {
                    asm("fma.rn.f32x2 %0, %1, %2, %0;"
                        : "+l"(acc[ii * 2 + 0][jj]) : "l"(a0p), "l"(b[jj]));
                    asm("fma.rn.f32x2 %0, %1, %2, %0;"
                        : "+l"(acc[ii * 2 + 1][jj]) : "l"(a1p), "l"(b[jj]));
                }
            }
        }
        __syncthreads();
    }
#pragma unroll
    for (int ii = 0; ii < 4; ii++) {
#pragma unroll
        for (int r = 0; r < 2; r++) {
            int n = n0 + ty * 2 + 32 * ii + r;
            if (n < N) {
#pragma unroll
                for (int jj = 0; jj < 4; jj++) {
                    float lo, hi;
                    asm("mov.b64 {%0, %1}, %2;"
                        : "=f"(lo), "=f"(hi) : "l"(acc[ii * 2 + r][jj]));
                    *(float2*)(C + (size_t)n * 256 + m0 + tx * 2 + 32 * jj)
                        = make_float2(lo, hi);
                }
            }
        }
    }
}

// =================== per-node attention scores ================================
__global__ void node_scores(const float* __restrict__ hp,
                            const float* __restrict__ a_src,
                            const float* __restrict__ a_dst,
                            float* __restrict__ s_src, float* __restrict__ s_dst,
                            int Hh, int F) {
    int n = blockIdx.x;
    int t = threadIdx.x;
    float v = hp[(size_t)n * DIM + t];
    __shared__ float shs[DIM];
    __shared__ float shd[DIM];
    shs[t] = v * a_src[t];
    shd[t] = v * a_dst[t];
    __syncthreads();
    for (int st = F >> 1; st > 0; st >>= 1) {
        if ((t & (F - 1)) < st) { shs[t] += shs[t + st]; shd[t] += shd[t + st]; }
        __syncthreads();
    }
    if ((t & (F - 1)) == 0) {
        int h = t / F;
        s_src[(size_t)n * Hh + h] = shs[t];
        s_dst[(size_t)n * Hh + h] = shd[t];
    }
}

// =================== CSR build ================================================
__global__ void count_deg(const int* __restrict__ dst, int* __restrict__ cnt, int E) {
    int e = blockIdx.x * blockDim.x + threadIdx.x;
    if (e < E) atomicAdd(&cnt[dst[e]], 1);
}

__global__ void scan_rowptr(const int* __restrict__ cnt, int* __restrict__ rowptr,
                            int* __restrict__ cursor, int N) {
    __shared__ int part[1024];
    int t = threadIdx.x;
    int chunk = (N + 1023) / 1024;
    int b = t * chunk;
    int e = min(b + chunk, N);
    int s = 0;
    for (int i = b; i < e; i++) s += cnt[i];
    part[t] = s;
    __syncthreads();
    for (int off = 1; off < 1024; off <<= 1) {
        int v = (t >= off) ? part[t - off] : 0;
        __syncthreads();
        part[t] += v;
        __syncthreads();
    }
    int run = (t > 0) ? part[t - 1] : 0;
    for (int i = b; i < e; i++) {
        rowptr[i] = run;
        cursor[i] = run;
        run += cnt[i];
    }
    if (t == 1023) rowptr[N] = part[1023];
}

__global__ void scatter_edges(const int* __restrict__ src, const int* __restrict__ dst,
                              int* __restrict__ cursor, int* __restrict__ srcs, int E) {
    int e = blockIdx.x * blockDim.x + threadIdx.x;
    if (e < E) {
        int p = atomicAdd(&cursor[dst[e]], 1);
        srcs[p] = src[e];
    }
}

// =================== fused per-node softmax + aggregation =====================
// One 256-thread block per dst node. All softmax state in shared memory.
template <int H>
__global__ __launch_bounds__(256) void attn_agg(
    const int* __restrict__ rowptr, const int* __restrict__ srcs,
    const float* __restrict__ ssrc, const float* __restrict__ sdst,
    const float* __restrict__ hp, float* __restrict__ out, int relu) {
    constexpr int F = DIM / H;
    int n = blockIdx.x;
    int tid = threadIdx.x;
    int beg = rowptr[n];
    int deg = rowptr[n + 1] - beg;

    __shared__ unsigned sh_key[H];
    __shared__ float sh_m[H];
    __shared__ float sh_sum[H];
    __shared__ float sh_sd[H];
    __shared__ int   sh_src[256];
    __shared__ float sh_ex[256 * H];

    if (tid < H) {
        sh_key[tid] = 0u;
        sh_sum[tid] = 0.f;
        sh_sd[tid] = sdst[(size_t)n * H + tid];
    }
    __syncthreads();

    // phase 1: per-head max over this node's edges (order-preserving uint key)
    for (int c0 = 0; c0 < deg; c0 += 256) {
        int i = c0 + tid;
        if (i < deg) {
            int s = srcs[beg + i];
#pragma unroll
            for (int h = 0; h < H; h++) {
                float v = ssrc[(size_t)s * H + h] + sh_sd[h];
                v = v > 0.f ? v : 0.2f * v;
                unsigned bb = __float_as_uint(v);
                unsigned key = (bb & 0x80000000u) ? ~bb : (bb | 0x80000000u);
                atomicMax(&sh_key[h], key);
            }
        }
    }
    __syncthreads();
    if (tid < H) {
        unsigned k = sh_key[tid];
        unsigned bb = (k & 0x80000000u) ? (k ^ 0x80000000u) : ~k;
        sh_m[tid] = __uint_as_float(bb);
    }
    __syncthreads();

    // phase 2: exp-sum (cache exp values + src ids for the first chunk)
    for (int c0 = 0; c0 < deg; c0 += 256) {
        int i = c0 + tid;
        if (i < deg) {
            int s = srcs[beg + i];
            if (c0 == 0) sh_src[tid] = s;
#pragma unroll
            for (int h = 0; h < H; h++) {
                float v = ssrc[(size_t)s * H + h] + sh_sd[h];
                v = v > 0.f ? v : 0.2f * v;
                float ex = __expf(v - sh_m[h]);
                if (c0 == 0) sh_ex[tid * H + h] = ex;
                atomicAdd(&sh_sum[h], ex);
            }
        }
    }
    __syncthreads();

    // phase 3: aggregate — thread tid owns output column tid
    int h = tid / F;
    float inv = 1.0f / (sh_sum[h] + 1e-16f);
    float acc = 0.f;
    for (int c0 = 0; c0 < deg; c0 += 256) {
        int cnt = min(256, deg - c0);
        if (c0 > 0) {  // refill chunk (rare: deg > 256)
            __syncthreads();
            int i = c0 + tid;
            if (i < deg) {
                int s = srcs[beg + i];
                sh_src[tid] = s;
#pragma unroll
                for (int hh = 0; hh < H; hh++) {
                    float v = ssrc[(size_t)s * H + hh] + sh_sd[hh];
                    v = v > 0.f ? v : 0.2f * v;
                    sh_ex[tid * H + hh] = __expf(v - sh_m[hh]);
                }
            }
            __syncthreads();
        }
#pragma unroll 4
        for (int i = 0; i < cnt; i++) {
            acc += sh_ex[i * H + h] * hp[(size_t)sh_src[i] * DIM + tid];
        }
    }
    float o = acc * inv;
    if (relu) o = fmaxf(o, 0.f);
    out[(size_t)n * DIM + tid] = o;
}

// ==============================================================================
extern "C" void kernel_launch(void* const* d_in, const int* in_sizes, int n_in,
                              void* d_out, int out_size) {
    const float* x      = (const float*)d_in[0];
    const int*   ei     = (const int*)  d_in[1];
    const float* W1     = (const float*)d_in[2];
    const float* a1_src = (const float*)d_in[3];
    const float* a1_dst = (const float*)d_in[4];
    const float* W2     = (const float*)d_in[5];
    const float* a2_src = (const float*)d_in[6];
    const float* a2_dst = (const float*)d_in[7];

    int N = in_sizes[0] / DIM;
    int E = in_sizes[1] / 2;
    const int* src = ei;
    const int* dst = ei + E;

    float *hp, *h, *ssrc, *sdst;
    int *cnt, *rowptr, *cursor, *srcs;
    cudaGetSymbolAddress((void**)&hp,     g_hp);
    cudaGetSymbolAddress((void**)&h,      g_h);
    cudaGetSymbolAddress((void**)&ssrc,   g_ssrc);
    cudaGetSymbolAddress((void**)&sdst,   g_sdst);
    cudaGetSymbolAddress((void**)&cnt,    g_cnt);
    cudaGetSymbolAddress((void**)&rowptr, g_rowptr);
    cudaGetSymbolAddress((void**)&cursor, g_cursor);
    cudaGetSymbolAddress((void**)&srcs,   g_srcs);

    float* out = (float*)d_out;

    // ---- CSR build (shared by both layers) ----
    cudaMemsetAsync(cnt, 0, (size_t)N * sizeof(int));
    count_deg<<<(E + 255) / 256, 256>>>(dst, cnt, E);
    scan_rowptr<<<1, 1024>>>(cnt, rowptr, cursor, N);
    scatter_edges<<<(E + 255) / 256, 256>>>(src, dst, cursor, srcs, E);

    dim3 gemm_grid((N + 127) / 128, DIM / 128);

    // ---- layer 1 (H=4, F=64) ----
    gemm_f32x2<<<gemm_grid, 256>>>(x, W1, hp, N);
    node_scores<<<N, 256>>>(hp, a1_src, a1_dst, ssrc, sdst, 4, 64);
    attn_agg<4><<<N, 256>>>(rowptr, srcs, ssrc, sdst, hp, h, 1);

    // ---- layer 2 (H=1, F=256) ----
    gemm_f32x2<<<gemm_grid, 256>>>(h, W2, hp, N);
    node_scores<<<N, 256>>>(hp, a2_src, a2_dst, ssrc, sdst, 1, 256);
    attn_agg<1><<<N, 256>>>(rowptr, srcs, ssrc, sdst, hp, out, 0);
}

// round 4
// speedup vs baseline: 1.3083x; 1.1589x over previous
#include <cuda_runtime.h>
#include <cuda_bf16.h>
#include <cstdint>

#define NN 50000
#define EE 850000
#define DIM 256

// ---------------- scratch (device globals; no allocation allowed) -------------
__device__ float g_hp[NN * DIM];
__device__ float g_h [NN * DIM];
__device__ float g_ssrc[NN * 4];
__device__ float g_sdst[NN * 4];
__device__ int   g_cnt   [NN];
__device__ int   g_rowptr[NN + 1];
__device__ int   g_cursor[NN];
__device__ int   g_srcs  [EE];

// ======================= helpers =============================================
__device__ __forceinline__ uint32_t smem_u32(const void* p) {
    uint32_t a;
    asm("{ .reg .u64 t; cvta.to.shared.u64 t, %1; cvt.u32.u64 %0, t; }" : "=r"(a) : "l"(p));
    return a;
}
#define SW128(b) ((b) ^ (((b) >> 3) & 0x70))

struct Bf4 { uint2 hi, lo; };
__device__ __forceinline__ Bf4 split4(float4 v) {
    Bf4 r;
    __nv_bfloat16 h0 = __float2bfloat16(v.x), h1 = __float2bfloat16(v.y);
    __nv_bfloat16 h2 = __float2bfloat16(v.z), h3 = __float2bfloat16(v.w);
    __nv_bfloat16 l0 = __float2bfloat16(v.x - __bfloat162float(h0));
    __nv_bfloat16 l1 = __float2bfloat16(v.y - __bfloat162float(h1));
    __nv_bfloat16 l2 = __float2bfloat16(v.z - __bfloat162float(h2));
    __nv_bfloat16 l3 = __float2bfloat16(v.w - __bfloat162float(h3));
    r.hi.x = (uint32_t)__bfloat16_as_ushort(h0) | ((uint32_t)__bfloat16_as_ushort(h1) << 16);
    r.hi.y = (uint32_t)__bfloat16_as_ushort(h2) | ((uint32_t)__bfloat16_as_ushort(h3) << 16);
    r.lo.x = (uint32_t)__bfloat16_as_ushort(l0) | ((uint32_t)__bfloat16_as_ushort(l1) << 16);
    r.lo.y = (uint32_t)__bfloat16_as_ushort(l2) | ((uint32_t)__bfloat16_as_ushort(l3) << 16);
    return r;
}

#define LDSM_X4(r0, r1, r2, r3, a) \
    asm volatile("ldmatrix.sync.aligned.m8n8.x4.shared.b16 {%0,%1,%2,%3}, [%4];" \
        : "=r"(r0), "=r"(r1), "=r"(r2), "=r"(r3) : "r"(a))

#define MMA_16816(d, a, b0, b1) \
    asm volatile("mma.sync.aligned.m16n8k16.row.col.f32.bf16.bf16.f32 " \
        "{%0,%1,%2,%3}, {%4,%5,%6,%7}, {%8,%9}, {%0,%1,%2,%3};" \
        : "+f"((d)[0]), "+f"((d)[1]), "+f"((d)[2]), "+f"((d)[3]) \
        : "r"((a)[0]), "r"((a)[1]), "r"((a)[2]), "r"((a)[3]), "r"(b0), "r"(b1))

// =================== HMMA bf16 split-3 GEMM ===================================
static constexpr int SM_AH = 0;
static constexpr int SM_AL = 16384;
static constexpr int SM_BH = 32768;
static constexpr int SM_BL = 49152;
static constexpr int SM_TOT = 65536 + 1024;

__global__ __launch_bounds__(256)
void gemm_hmma(const float* __restrict__ A, const float* __restrict__ B,
               float* __restrict__ C, int N) {
    extern __shared__ char smem_raw[];
    uint32_t sb0 = smem_u32(smem_raw);
    uint32_t sb  = (sb0 + 1023u) & ~1023u;
    char* smem = smem_raw + (sb - sb0);   // 1024-aligned generic pointer

    const int tid  = threadIdx.x;
    const int lane = tid & 31;
    const int wid  = tid >> 5;
    const int n0 = blockIdx.x * 128;
    const int m0 = blockIdx.y * 128;
    const int m_warp = (wid >> 1) * 32;
    const int n_warp = (wid & 1) * 64;

    float acc[2][8][4];
#pragma unroll
    for (int i = 0; i < 2; i++)
#pragma unroll
        for (int j = 0; j < 8; j++)
#pragma unroll
            for (int q = 0; q < 4; q++) acc[i][j][q] = 0.f;

    const int a_row = (lane & 15);
    const int a_khi = (lane >> 4) << 3;
    const int b_row = (lane & 7) + ((lane >> 4) << 3);
    const int b_khi = ((lane >> 3) & 1) << 3;

    for (int c = 0; c < 4; c++) {
#pragma unroll
        for (int i = 0; i < 8; i++) {
            int f = tid + 256 * i;
            int r = f >> 4;
            int k4 = (f & 15) << 2;
            int row = n0 + r;
            float4 v = (row < N) ? *(const float4*)(A + (size_t)row * 256 + c * 64 + k4)
                                 : make_float4(0.f, 0.f, 0.f, 0.f);
            Bf4 s = split4(v);
            uint32_t off = SW128((uint32_t)(r * 128 + k4 * 2));
            *(uint2*)(smem + SM_AH + off) = s.hi;
            *(uint2*)(smem + SM_AL + off) = s.lo;
        }
#pragma unroll
        for (int i = 0; i < 8; i++) {
            int f = tid + 256 * i;
            int r = f >> 4;
            int k4 = (f & 15) << 2;
            float4 v = *(const float4*)(B + (size_t)(m0 + r) * 256 + c * 64 + k4);
            Bf4 s = split4(v);
            uint32_t off = SW128((uint32_t)(r * 128 + k4 * 2));
            *(uint2*)(smem + SM_BH + off) = s.hi;
            *(uint2*)(smem + SM_BL + off) = s.lo;
        }
        __syncthreads();

#pragma unroll
        for (int ks = 0; ks < 4; ks++) {
            int kb_a = ks * 16 + a_khi;
            int kb_b = ks * 16 + b_khi;

            uint32_t ah[2][4], bh[4][4];
#pragma unroll
            for (int mt = 0; mt < 2; mt++) {
                uint32_t ad = sb + SM_AH +
                    SW128((uint32_t)((m_warp + mt * 16 + a_row) * 128 + kb_a * 2));
                LDSM_X4(ah[mt][0], ah[mt][1], ah[mt][2], ah[mt][3], ad);
            }
#pragma unroll
            for (int p = 0; p < 4; p++) {
                uint32_t bd = sb + SM_BH +
                    SW128((uint32_t)((n_warp + p * 16 + b_row) * 128 + kb_b * 2));
                LDSM_X4(bh[p][0], bh[p][1], bh[p][2], bh[p][3], bd);
            }
#pragma unroll
            for (int mt = 0; mt < 2; mt++)
#pragma unroll
                for (int p = 0; p < 4; p++) {
                    MMA_16816(acc[mt][p * 2 + 0], ah[mt], bh[p][0], bh[p][1]);
                    MMA_16816(acc[mt][p * 2 + 1], ah[mt], bh[p][2], bh[p][3]);
                }

            uint32_t bl[4][4];
#pragma unroll
            for (int p = 0; p < 4; p++) {
                uint32_t bd = sb + SM_BL +
                    SW128((uint32_t)((n_warp + p * 16 + b_row) * 128 + kb_b * 2));
                LDSM_X4(bl[p][0], bl[p][1], bl[p][2], bl[p][3], bd);
            }
#pragma unroll
            for (int mt = 0; mt < 2; mt++)
#pragma unroll
                for (int p = 0; p < 4; p++) {
                    MMA_16816(acc[mt][p * 2 + 0], ah[mt], bl[p][0], bl[p][1]);
                    MMA_16816(acc[mt][p * 2 + 1], ah[mt], bl[p][2], bl[p][3]);
                }

            uint32_t al[2][4];
#pragma unroll
            for (int mt = 0; mt < 2; mt++) {
                uint32_t ad = sb + SM_AL +
                    SW128((uint32_t)((m_warp + mt * 16 + a_row) * 128 + kb_a * 2));
                LDSM_X4(al[mt][0], al[mt][1], al[mt][2], al[mt][3], ad);
            }
#pragma unroll
            for (int mt = 0; mt < 2; mt++)
#pragma unroll
                for (int p = 0; p < 4; p++) {
                    MMA_16816(acc[mt][p * 2 + 0], al[mt], bh[p][0], bh[p][1]);
                    MMA_16816(acc[mt][p * 2 + 1], al[mt], bh[p][2], bh[p][3]);
                }
        }
        __syncthreads();
    }

#pragma unroll
    for (int mt = 0; mt < 2; mt++) {
        int row = n0 + m_warp + mt * 16 + (lane >> 2);
#pragma unroll
        for (int nt = 0; nt < 8; nt++) {
            int col = m0 + n_warp + nt * 8 + (lane & 3) * 2;
            if (row < N)
                *(float2*)(C + (size_t)row * 256 + col)
                    = make_float2(acc[mt][nt][0], acc[mt][nt][1]);
            if (row + 8 < N)
                *(float2*)(C + (size_t)(row + 8) * 256 + col)
                    = make_float2(acc[mt][nt][2], acc[mt][nt][3]);
        }
    }
}

// =================== per-node attention scores ================================
__global__ void node_scores(const float* __restrict__ hp,
                            const float* __restrict__ a_src,
                            const float* __restrict__ a_dst,
                            float* __restrict__ s_src, float* __restrict__ s_dst,
                            int Hh, int F) {
    int n = blockIdx.x;
    int t = threadIdx.x;
    float v = hp[(size_t)n * DIM + t];
    __shared__ float shs[DIM];
    __shared__ float shd[DIM];
    shs[t] = v * a_src[t];
    shd[t] = v * a_dst[t];
    __syncthreads();
    for (int st = F >> 1; st > 0; st >>= 1) {
        if ((t & (F - 1)) < st) { shs[t] += shs[t + st]; shd[t] += shd[t + st]; }
        __syncthreads();
    }
    if ((t & (F - 1)) == 0) {
        int h = t / F;
        s_src[(size_t)n * Hh + h] = shs[t];
        s_dst[(size_t)n * Hh + h] = shd[t];
    }
}

// =================== CSR build ================================================
__global__ void count_deg(const int* __restrict__ dst, int* __restrict__ cnt, int E) {
    int e = blockIdx.x * blockDim.x + threadIdx.x;
    if (e < E) atomicAdd(&cnt[dst[e]], 1);
}

__global__ void scan_rowptr(const int* __restrict__ cnt, int* __restrict__ rowptr,
                            int* __restrict__ cursor, int N) {
    __shared__ int part[1024];
    int t = threadIdx.x;
    int chunk = (N + 1023) / 1024;
    int b = t * chunk;
    int e = min(b + chunk, N);
    int s = 0;
    for (int i = b; i < e; i++) s += cnt[i];
    part[t] = s;
    __syncthreads();
    for (int off = 1; off < 1024; off <<= 1) {
        int v = (t >= off) ? part[t - off] : 0;
        __syncthreads();
        part[t] += v;
        __syncthreads();
    }
    int run = (t > 0) ? part[t - 1] : 0;
    for (int i = b; i < e; i++) {
        rowptr[i] = run;
        cursor[i] = run;
        run += cnt[i];
    }
    if (t == 1023) rowptr[N] = part[1023];
}

__global__ void scatter_edges(const int* __restrict__ src, const int* __restrict__ dst,
                              int* __restrict__ cursor, int* __restrict__ srcs, int E) {
    int e = blockIdx.x * blockDim.x + threadIdx.x;
    if (e < E) {
        int p = atomicAdd(&cursor[dst[e]], 1);
        srcs[p] = src[e];
    }
}

// =================== fused per-node softmax + aggregation =====================
template <int H>
__global__ __launch_bounds__(256) void attn_agg(
    const int* __restrict__ rowptr, const int* __restrict__ srcs,
    const float* __restrict__ ssrc, const float* __restrict__ sdst,
    const float* __restrict__ hp, float* __restrict__ out, int relu) {
    constexpr int F = DIM / H;
    int n = blockIdx.x;
    int tid = threadIdx.x;
    int beg = rowptr[n];
    int deg = rowptr[n + 1] - beg;

    __shared__ unsigned sh_key[H];
    __shared__ float sh_m[H];
    __shared__ float sh_sum[H];
    __shared__ float sh_sd[H];
    __shared__ int   sh_src[256];
    __shared__ float sh_ex[256 * H];

    if (tid < H) {
        sh_key[tid] = 0u;
        sh_sum[tid] = 0.f;
        sh_sd[tid] = sdst[(size_t)n * H + tid];
    }
    __syncthreads();

    for (int c0 = 0; c0 < deg; c0 += 256) {
        int i = c0 + tid;
        if (i < deg) {
            int s = srcs[beg + i];
#pragma unroll
            for (int h = 0; h < H; h++) {
                float v = ssrc[(size_t)s * H + h] + sh_sd[h];
                v = v > 0.f ? v : 0.2f * v;
                unsigned bb = __float_as_uint(v);
                unsigned key = (bb & 0x80000000u) ? ~bb : (bb | 0x80000000u);
                atomicMax(&sh_key[h], key);
            }
        }
    }
    __syncthreads();
    if (tid < H) {
        unsigned k = sh_key[tid];
        unsigned bb = (k & 0x80000000u) ? (k ^ 0x80000000u) : ~k;
        sh_m[tid] = __uint_as_float(bb);
    }
    __syncthreads();

    for (int c0 = 0; c0 < deg; c0 += 256) {
        int i = c0 + tid;
        if (i < deg) {
            int s = srcs[beg + i];
            if (c0 == 0) sh_src[tid] = s;
#pragma unroll
            for (int h = 0; h < H; h++) {
                float v = ssrc[(size_t)s * H + h] + sh_sd[h];
                v = v > 0.f ? v : 0.2f * v;
                float ex = __expf(v - sh_m[h]);
                if (c0 == 0) sh_ex[tid * H + h] = ex;
                atomicAdd(&sh_sum[h], ex);
            }
        }
    }
    __syncthreads();

    int h = tid / F;
    float inv = 1.0f / (sh_sum[h] + 1e-16f);
    float acc = 0.f;
    for (int c0 = 0; c0 < deg; c0 += 256) {
        int cnt = min(256, deg - c0);
        if (c0 > 0) {
            __syncthreads();
            int i = c0 + tid;
            if (i < deg) {
                int s = srcs[beg + i];
                sh_src[tid] = s;
#pragma unroll
                for (int hh = 0; hh < H; hh++) {
                    float v = ssrc[(size_t)s * H + hh] + sh_sd[hh];
                    v = v > 0.f ? v : 0.2f * v;
                    sh_ex[tid * H + hh] = __expf(v - sh_m[hh]);
                }
            }
            __syncthreads();
        }
#pragma unroll 4
        for (int i = 0; i < cnt; i++) {
            acc += sh_ex[i * H + h] * hp[(size_t)sh_src[i] * DIM + tid];
        }
    }
    float o = acc * inv;
    if (relu) o = fmaxf(o, 0.f);
    out[(size_t)n * DIM + tid] = o;
}

// ==============================================================================
extern "C" void kernel_launch(void* const* d_in, const int* in_sizes, int n_in,
                              void* d_out, int out_size) {
    const float* x      = (const float*)d_in[0];
    const int*   ei     = (const int*)  d_in[1];
    const float* W1     = (const float*)d_in[2];
    const float* a1_src = (const float*)d_in[3];
    const float* a1_dst = (const float*)d_in[4];
    const float* W2     = (const float*)d_in[5];
    const float* a2_src = (const float*)d_in[6];
    const float* a2_dst = (const float*)d_in[7];

    int N = in_sizes[0] / DIM;
    int E = in_sizes[1] / 2;
    const int* src = ei;
    const int* dst = ei + E;

    float *hp, *h, *ssrc, *sdst;
    int *cnt, *rowptr, *cursor, *srcs;
    cudaGetSymbolAddress((void**)&hp,     g_hp);
    cudaGetSymbolAddress((void**)&h,      g_h);
    cudaGetSymbolAddress((void**)&ssrc,   g_ssrc);
    cudaGetSymbolAddress((void**)&sdst,   g_sdst);
    cudaGetSymbolAddress((void**)&cnt,    g_cnt);
    cudaGetSymbolAddress((void**)&rowptr, g_rowptr);
    cudaGetSymbolAddress((void**)&cursor, g_cursor);
    cudaGetSymbolAddress((void**)&srcs,   g_srcs);

    float* out = (float*)d_out;

    cudaFuncSetAttribute(gemm_hmma, cudaFuncAttributeMaxDynamicSharedMemorySize, SM_TOT);

    cudaMemsetAsync(cnt, 0, (size_t)N * sizeof(int));
    count_deg<<<(E + 255) / 256, 256>>>(dst, cnt, E);
    scan_rowptr<<<1, 1024>>>(cnt, rowptr, cursor, N);
    scatter_edges<<<(E + 255) / 256, 256>>>(src, dst, cursor, srcs, E);

    dim3 gemm_grid((N + 127) / 128, 2);

    gemm_hmma<<<gemm_grid, 256, SM_TOT>>>(x, W1, hp, N);
    node_scores<<<N, 256>>>(hp, a1_src, a1_dst, ssrc, sdst, 4, 64);
    attn_agg<4><<<N, 256>>>(rowptr, srcs, ssrc, sdst, hp, h, 1);

    gemm_hmma<<<gemm_grid, 256, SM_TOT>>>(h, W2, hp, N);
    node_scores<<<N, 256>>>(hp, a2_src, a2_dst, ssrc, sdst, 1, 256);
    attn_agg<1><<<N, 256>>>(rowptr, srcs, ssrc, sdst, hp, out, 0);
}

// round 5
// speedup vs baseline: 1.9298x; 1.4751x over previous
#include <cuda_runtime.h>
#include <cuda_bf16.h>
#include <cstdint>

#define NN 50000
#define EE 850000
#define DIM 256

// ---------------- scratch (device globals; no allocation allowed) -------------
__device__ float g_hp[NN * DIM];                 // GEMM output (fp32)
__device__ __nv_bfloat16 g_ah[NN * DIM];         // A operand hi (x split, then h)
__device__ __nv_bfloat16 g_al[NN * DIM];         // A operand lo
__device__ __nv_bfloat16 g_wh[DIM * DIM];        // W hi
__device__ __nv_bfloat16 g_wl[DIM * DIM];        // W lo
__device__ float g_ssrc[NN * 4];
__device__ float g_sdst[NN * 4];
__device__ int   g_cnt   [NN];
__device__ int   g_rowptr[NN + 1];
__device__ int   g_cursor[NN];
__device__ int   g_srcs  [EE];

// ======================= helpers =============================================
__device__ __forceinline__ uint32_t smem_u32(const void* p) {
    uint32_t a;
    asm("{ .reg .u64 t; cvta.to.shared.u64 t, %1; cvt.u32.u64 %0, t; }" : "=r"(a) : "l"(p));
    return a;
}
#define SW128(b) ((b) ^ (((b) >> 3) & 0x70))

struct Bf4 { uint2 hi, lo; };
__device__ __forceinline__ Bf4 split4(float4 v) {
    Bf4 r;
    __nv_bfloat16 h0 = __float2bfloat16(v.x), h1 = __float2bfloat16(v.y);
    __nv_bfloat16 h2 = __float2bfloat16(v.z), h3 = __float2bfloat16(v.w);
    __nv_bfloat16 l0 = __float2bfloat16(v.x - __bfloat162float(h0));
    __nv_bfloat16 l1 = __float2bfloat16(v.y - __bfloat162float(h1));
    __nv_bfloat16 l2 = __float2bfloat16(v.z - __bfloat162float(h2));
    __nv_bfloat16 l3 = __float2bfloat16(v.w - __bfloat162float(h3));
    r.hi.x = (uint32_t)__bfloat16_as_ushort(h0) | ((uint32_t)__bfloat16_as_ushort(h1) << 16);
    r.hi.y = (uint32_t)__bfloat16_as_ushort(h2) | ((uint32_t)__bfloat16_as_ushort(h3) << 16);
    r.lo.x = (uint32_t)__bfloat16_as_ushort(l0) | ((uint32_t)__bfloat16_as_ushort(l1) << 16);
    r.lo.y = (uint32_t)__bfloat16_as_ushort(l2) | ((uint32_t)__bfloat16_as_ushort(l3) << 16);
    return r;
}

#define LDSM_X4(r0, r1, r2, r3, a) \
    asm volatile("ldmatrix.sync.aligned.m8n8.x4.shared.b16 {%0,%1,%2,%3}, [%4];" \
        : "=r"(r0), "=r"(r1), "=r"(r2), "=r"(r3) : "r"(a))

#define MMA_16816(d, a, b0, b1) \
    asm volatile("mma.sync.aligned.m16n8k16.row.col.f32.bf16.bf16.f32 " \
        "{%0,%1,%2,%3}, {%4,%5,%6,%7}, {%8,%9}, {%0,%1,%2,%3};" \
        : "+f"((d)[0]), "+f"((d)[1]), "+f"((d)[2]), "+f"((d)[3]) \
        : "r"((a)[0]), "r"((a)[1]), "r"((a)[2]), "r"((a)[3]), "r"(b0), "r"(b1))

#define CP16(dst, src, sz) \
    asm volatile("cp.async.cg.shared.global [%0], [%1], 16, %2;" \
        :: "r"(dst), "l"(src), "r"(sz) : "memory")
#define CP_COMMIT() asm volatile("cp.async.commit_group;" ::: "memory")
#define CP_WAIT1() asm volatile("cp.async.wait_group 1;" ::: "memory")
#define CP_WAIT0() asm volatile("cp.async.wait_group 0;" ::: "memory")

// =================== fp32 -> bf16 hi/lo split (elementwise) ===================
__global__ void split_f4(const float* __restrict__ in, __nv_bfloat16* __restrict__ hi,
                         __nv_bfloat16* __restrict__ lo, int n4) {
    int i = blockIdx.x * blockDim.x + threadIdx.x;
    if (i >= n4) return;
    Bf4 s = split4(((const float4*)in)[i]);
    ((uint2*)hi)[i] = s.hi;
    ((uint2*)lo)[i] = s.lo;
}

// =================== HMMA bf16 split-3 GEMM (pre-split, cp.async pipelined) ===
// C[n][m] = sum_k A[n][k]*B[m][k]. Tiles: CTA 128x128, warp 32x64, K chunks 64.
static constexpr int BUF = 65536;      // per-buffer: AH|AL|BH|BL each 16KB
static constexpr int SM_GEMM = 2 * BUF + 1024;

__global__ __launch_bounds__(256)
void gemm_bf16(const __nv_bfloat16* __restrict__ Ah, const __nv_bfloat16* __restrict__ Al,
               const __nv_bfloat16* __restrict__ Bh, const __nv_bfloat16* __restrict__ Bl,
               float* __restrict__ C, int N) {
    extern __shared__ char smem_raw[];
    uint32_t sb0 = smem_u32(smem_raw);
    uint32_t sb  = (sb0 + 1023u) & ~1023u;

    const int tid  = threadIdx.x;
    const int lane = tid & 31;
    const int wid  = tid >> 5;
    const int n0 = blockIdx.x * 128;
    const int m0 = blockIdx.y * 128;
    const int m_warp = (wid >> 1) * 32;
    const int n_warp = (wid & 1) * 64;

    const char* pAh = (const char*)Ah;
    const char* pAl = (const char*)Al;
    const char* pBh = (const char*)Bh;
    const char* pBl = (const char*)Bl;

    // per-thread load mapping: 4 x 16B per tile (1024 chunks / 256 threads)
    const int lr  = tid >> 1;              // used as r base with i*? compute per i
    (void)lr;

    auto load_chunk = [&](int c, int b) {
#pragma unroll
        for (int i = 0; i < 4; i++) {
            int idx = tid + 256 * i;          // 0..1023
            int r   = idx >> 3;               // row 0..127
            int k16 = (idx & 7) * 16;         // byte offset in 128B row
            uint32_t off = SW128((uint32_t)(r * 128 + k16));
            uint32_t base = sb + b * BUF;
            // A rows may be OOB -> zero-fill
            int arow = n0 + r;
            int pa = (arow < N) ? 16 : 0;
            size_t ga = (size_t)min(arow, N - 1) * 512 + (size_t)c * 128 + k16;
            CP16(base + 0     + off, pAh + ga, pa);
            CP16(base + 16384 + off, pAl + ga, pa);
            size_t gb = (size_t)(m0 + r) * 512 + (size_t)c * 128 + k16;
            CP16(base + 32768 + off, pBh + gb, 16);
            CP16(base + 49152 + off, pBl + gb, 16);
        }
        CP_COMMIT();
    };

    float acc[2][8][4];
#pragma unroll
    for (int i = 0; i < 2; i++)
#pragma unroll
        for (int j = 0; j < 8; j++)
#pragma unroll
            for (int q = 0; q < 4; q++) acc[i][j][q] = 0.f;

    const int a_row = (lane & 15);
    const int a_khi = (lane >> 4) << 3;
    const int b_row = (lane & 7) + ((lane >> 4) << 3);
    const int b_khi = ((lane >> 3) & 1) << 3;

    load_chunk(0, 0);

    for (int c = 0; c < 4; c++) {
        if (c < 3) load_chunk(c + 1, (c + 1) & 1);
        if (c < 3) { CP_WAIT1(); } else { CP_WAIT0(); }
        __syncthreads();

        uint32_t base = sb + (c & 1) * BUF;
#pragma unroll
        for (int ks = 0; ks < 4; ks++) {
            int kb_a = ks * 16 + a_khi;
            int kb_b = ks * 16 + b_khi;

            uint32_t ah[2][4], bh[4][4];
#pragma unroll
            for (int mt = 0; mt < 2; mt++) {
                uint32_t ad = base + 0 +
                    SW128((uint32_t)((m_warp + mt * 16 + a_row) * 128 + kb_a * 2));
                LDSM_X4(ah[mt][0], ah[mt][1], ah[mt][2], ah[mt][3], ad);
            }
#pragma unroll
            for (int p = 0; p < 4; p++) {
                uint32_t bd = base + 32768 +
                    SW128((uint32_t)((n_warp + p * 16 + b_row) * 128 + kb_b * 2));
                LDSM_X4(bh[p][0], bh[p][1], bh[p][2], bh[p][3], bd);
            }
#pragma unroll
            for (int mt = 0; mt < 2; mt++)
#pragma unroll
                for (int p = 0; p < 4; p++) {
                    MMA_16816(acc[mt][p * 2 + 0], ah[mt], bh[p][0], bh[p][1]);
                    MMA_16816(acc[mt][p * 2 + 1], ah[mt], bh[p][2], bh[p][3]);
                }

            uint32_t bl[4][4];
#pragma unroll
            for (int p = 0; p < 4; p++) {
                uint32_t bd = base + 49152 +
                    SW128((uint32_t)((n_warp + p * 16 + b_row) * 128 + kb_b * 2));
                LDSM_X4(bl[p][0], bl[p][1], bl[p][2], bl[p][3], bd);
            }
#pragma unroll
            for (int mt = 0; mt < 2; mt++)
#pragma unroll
                for (int p = 0; p < 4; p++) {
                    MMA_16816(acc[mt][p * 2 + 0], ah[mt], bl[p][0], bl[p][1]);
                    MMA_16816(acc[mt][p * 2 + 1], ah[mt], bl[p][2], bl[p][3]);
                }

            uint32_t al[2][4];
#pragma unroll
            for (int mt = 0; mt < 2; mt++) {
                uint32_t ad = base + 16384 +
                    SW128((uint32_t)((m_warp + mt * 16 + a_row) * 128 + kb_a * 2));
                LDSM_X4(al[mt][0], al[mt][1], al[mt][2], al[mt][3], ad);
            }
#pragma unroll
            for (int mt = 0; mt < 2; mt++)
#pragma unroll
                for (int p = 0; p < 4; p++) {
                    MMA_16816(acc[mt][p * 2 + 0], al[mt], bh[p][0], bh[p][1]);
                    MMA_16816(acc[mt][p * 2 + 1], al[mt], bh[p][2], bh[p][3]);
                }
        }
        __syncthreads();
    }

#pragma unroll
    for (int mt = 0; mt < 2; mt++) {
        int row = n0 + m_warp + mt * 16 + (lane >> 2);
#pragma unroll
        for (int nt = 0; nt < 8; nt++) {
            int col = m0 + n_warp + nt * 8 + (lane & 3) * 2;
            if (row < N)
                *(float2*)(C + (size_t)row * 256 + col)
                    = make_float2(acc[mt][nt][0], acc[mt][nt][1]);
            if (row + 8 < N)
                *(float2*)(C + (size_t)(row + 8) * 256 + col)
                    = make_float2(acc[mt][nt][2], acc[mt][nt][3]);
        }
    }
}

// =================== per-node attention scores ================================
__global__ void node_scores(const float* __restrict__ hp,
                            const float* __restrict__ a_src,
                            const float* __restrict__ a_dst,
                            float* __restrict__ s_src, float* __restrict__ s_dst,
                            int Hh, int F) {
    int n = blockIdx.x;
    int t = threadIdx.x;
    float v = hp[(size_t)n * DIM + t];
    __shared__ float shs[DIM];
    __shared__ float shd[DIM];
    shs[t] = v * a_src[t];
    shd[t] = v * a_dst[t];
    __syncthreads();
    for (int st = F >> 1; st > 0; st >>= 1) {
        if ((t & (F - 1)) < st) { shs[t] += shs[t + st]; shd[t] += shd[t + st]; }
        __syncthreads();
    }
    if ((t & (F - 1)) == 0) {
        int h = t / F;
        s_src[(size_t)n * Hh + h] = shs[t];
        s_dst[(size_t)n * Hh + h] = shd[t];
    }
}

// =================== CSR build ================================================
__global__ void count_deg(const int* __restrict__ dst, int* __restrict__ cnt, int E) {
    int e = blockIdx.x * blockDim.x + threadIdx.x;
    if (e < E) atomicAdd(&cnt[dst[e]], 1);
}

__global__ void scan_rowptr(const int* __restrict__ cnt, int* __restrict__ rowptr,
                            int* __restrict__ cursor, int N) {
    __shared__ int part[1024];
    int t = threadIdx.x;
    int chunk = (N + 1023) / 1024;
    int b = t * chunk;
    int e = min(b + chunk, N);
    int s = 0;
    for (int i = b; i < e; i++) s += cnt[i];
    part[t] = s;
    __syncthreads();
    for (int off = 1; off < 1024; off <<= 1) {
        int v = (t >= off) ? part[t - off] : 0;
        __syncthreads();
        part[t] += v;
        __syncthreads();
    }
    int run = (t > 0) ? part[t - 1] : 0;
    for (int i = b; i < e; i++) {
        rowptr[i] = run;
        cursor[i] = run;
        run += cnt[i];
    }
    if (t == 1023) rowptr[N] = part[1023];
}

__global__ void scatter_edges(const int* __restrict__ src, const int* __restrict__ dst,
                              int* __restrict__ cursor, int* __restrict__ srcs, int E) {
    int e = blockIdx.x * blockDim.x + threadIdx.x;
    if (e < E) {
        int p = atomicAdd(&cursor[dst[e]], 1);
        srcs[p] = src[e];
    }
}

// =================== fused per-node softmax + aggregation =====================
// 128 threads/block; thread owns output cols (2t, 2t+1).
// SPLIT=true: apply relu, write bf16 hi/lo (layer-1 h feeding GEMM2).
template <int H, bool SPLIT>
__global__ __launch_bounds__(128) void attn_agg(
    const int* __restrict__ rowptr, const int* __restrict__ srcs,
    const float* __restrict__ ssrc, const float* __restrict__ sdst,
    const float* __restrict__ hp, float* __restrict__ out,
    __nv_bfloat16* __restrict__ oh, __nv_bfloat16* __restrict__ ol) {
    constexpr int F = DIM / H;
    int n = blockIdx.x;
    int tid = threadIdx.x;
    int beg = rowptr[n];
    int deg = rowptr[n + 1] - beg;

    __shared__ unsigned sh_key[H];
    __shared__ float sh_m[H];
    __shared__ float sh_sum[H];
    __shared__ float sh_sd[H];
    __shared__ int   sh_src[128];
    __shared__ float sh_ex[128 * H];

    if (tid < H) {
        sh_key[tid] = 0u;
        sh_sum[tid] = 0.f;
        sh_sd[tid] = sdst[(size_t)n * H + tid];
    }
    __syncthreads();

    // phase A: logits for chunk 0 cached in smem; max over all edges
    if (tid < deg) {
        int s = srcs[beg + tid];
        sh_src[tid] = s;
#pragma unroll
        for (int h = 0; h < H; h++) {
            float v = ssrc[(size_t)s * H + h] + sh_sd[h];
            v = v > 0.f ? v : 0.2f * v;
            sh_ex[tid * H + h] = v;
            unsigned bb = __float_as_uint(v);
            unsigned key = (bb & 0x80000000u) ? ~bb : (bb | 0x80000000u);
            atomicMax(&sh_key[h], key);
        }
    }
    for (int c0 = 128; c0 < deg; c0 += 128) {      // rare: deg > 128
        int i = c0 + tid;
        if (i < deg) {
            int s = srcs[beg + i];
#pragma unroll
            for (int h = 0; h < H; h++) {
                float v = ssrc[(size_t)s * H + h] + sh_sd[h];
                v = v > 0.f ? v : 0.2f * v;
                unsigned bb = __float_as_uint(v);
                unsigned key = (bb & 0x80000000u) ? ~bb : (bb | 0x80000000u);
                atomicMax(&sh_key[h], key);
            }
        }
    }
    __syncthreads();
    if (tid < H) {
        unsigned k = sh_key[tid];
        unsigned bb = (k & 0x80000000u) ? (k ^ 0x80000000u) : ~k;
        sh_m[tid] = __uint_as_float(bb);
    }
    __syncthreads();

    // phase B: exp + sum (chunk 0 in-place; tails recomputed)
    if (tid < deg) {
#pragma unroll
        for (int h = 0; h < H; h++) {
            float ex = __expf(sh_ex[tid * H + h] - sh_m[h]);
            sh_ex[tid * H + h] = ex;
            atomicAdd(&sh_sum[h], ex);
        }
    }
    for (int c0 = 128; c0 < deg; c0 += 128) {
        int i = c0 + tid;
        if (i < deg) {
            int s = srcs[beg + i];
#pragma unroll
            for (int h = 0; h < H; h++) {
                float v = ssrc[(size_t)s * H + h] + sh_sd[h];
                v = v > 0.f ? v : 0.2f * v;
                atomicAdd(&sh_sum[h], __expf(v - sh_m[h]));
            }
        }
    }
    __syncthreads();

    // phase C: aggregate (thread owns cols 2t, 2t+1; both in head h)
    int col = 2 * tid;
    int h = col / F;
    float inv = 1.0f / (sh_sum[h] + 1e-16f);
    float ax = 0.f, ay = 0.f;
    int cnt0 = min(deg, 128);
#pragma unroll 4
    for (int i = 0; i < cnt0; i++) {
        float w = sh_ex[i * H + h];
        float2 v = *(const float2*)(hp + (size_t)sh_src[i] * DIM + col);
        ax += w * v.x; ay += w * v.y;
    }
    for (int c0 = 128; c0 < deg; c0 += 128) {      // rare tail
        __syncthreads();
        int i = c0 + tid;
        if (i < deg) {
            int s = srcs[beg + i];
            sh_src[tid] = s;
#pragma unroll
            for (int hh = 0; hh < H; hh++) {
                float v = ssrc[(size_t)s * H + hh] + sh_sd[hh];
                v = v > 0.f ? v : 0.2f * v;
                sh_ex[tid * H + hh] = __expf(v - sh_m[hh]);
            }
        }
        __syncthreads();
        int cnt = min(128, deg - c0);
#pragma unroll 4
        for (int i2 = 0; i2 < cnt; i2++) {
            float w = sh_ex[i2 * H + h];
            float2 v = *(const float2*)(hp + (size_t)sh_src[i2] * DIM + col);
            ax += w * v.x; ay += w * v.y;
        }
    }
    ax *= inv; ay *= inv;

    if (SPLIT) {
        ax = fmaxf(ax, 0.f); ay = fmaxf(ay, 0.f);
        __nv_bfloat16 hx = __float2bfloat16(ax), hy = __float2bfloat16(ay);
        __nv_bfloat16 lx = __float2bfloat16(ax - __bfloat162float(hx));
        __nv_bfloat16 ly = __float2bfloat16(ay - __bfloat162float(hy));
        uint32_t ph = (uint32_t)__bfloat16_as_ushort(hx) | ((uint32_t)__bfloat16_as_ushort(hy) << 16);
        uint32_t pl = (uint32_t)__bfloat16_as_ushort(lx) | ((uint32_t)__bfloat16_as_ushort(ly) << 16);
        *(uint32_t*)((char*)oh + ((size_t)n * DIM + col) * 2) = ph;
        *(uint32_t*)((char*)ol + ((size_t)n * DIM + col) * 2) = pl;
    } else {
        *(float2*)(out + (size_t)n * DIM + col) = make_float2(ax, ay);
    }
}

// ==============================================================================
extern "C" void kernel_launch(void* const* d_in, const int* in_sizes, int n_in,
                              void* d_out, int out_size) {
    const float* x      = (const float*)d_in[0];
    const int*   ei     = (const int*)  d_in[1];
    const float* W1     = (const float*)d_in[2];
    const float* a1_src = (const float*)d_in[3];
    const float* a1_dst = (const float*)d_in[4];
    const float* W2     = (const float*)d_in[5];
    const float* a2_src = (const float*)d_in[6];
    const float* a2_dst = (const float*)d_in[7];

    int N = in_sizes[0] / DIM;
    int E = in_sizes[1] / 2;
    const int* src = ei;
    const int* dst = ei + E;

    float *hp, *ssrc, *sdst;
    __nv_bfloat16 *ah, *al, *wh, *wl;
    int *cnt, *rowptr, *cursor, *srcs;
    cudaGetSymbolAddress((void**)&hp,     g_hp);
    cudaGetSymbolAddress((void**)&ah,     g_ah);
    cudaGetSymbolAddress((void**)&al,     g_al);
    cudaGetSymbolAddress((void**)&wh,     g_wh);
    cudaGetSymbolAddress((void**)&wl,     g_wl);
    cudaGetSymbolAddress((void**)&ssrc,   g_ssrc);
    cudaGetSymbolAddress((void**)&sdst,   g_sdst);
    cudaGetSymbolAddress((void**)&cnt,    g_cnt);
    cudaGetSymbolAddress((void**)&rowptr, g_rowptr);
    cudaGetSymbolAddress((void**)&cursor, g_cursor);
    cudaGetSymbolAddress((void**)&srcs,   g_srcs);

    float* out = (float*)d_out;

    cudaFuncSetAttribute(gemm_bf16, cudaFuncAttributeMaxDynamicSharedMemorySize, SM_GEMM);

    // ---- CSR build ----
    cudaMemsetAsync(cnt, 0, (size_t)N * sizeof(int));
    count_deg<<<(E + 255) / 256, 256>>>(dst, cnt, E);
    scan_rowptr<<<1, 1024>>>(cnt, rowptr, cursor, N);
    scatter_edges<<<(E + 255) / 256, 256>>>(src, dst, cursor, srcs, E);

    dim3 gemm_grid((N + 127) / 128, 2);
    int n4x = N * DIM / 4;
    int n4w = DIM * DIM / 4;

    // ---- layer 1 (H=4, F=64) ----
    split_f4<<<(n4w + 127) / 128, 128>>>(W1, wh, wl, n4w);
    split_f4<<<(n4x + 127) / 128, 128>>>(x, ah, al, n4x);
    gemm_bf16<<<gemm_grid, 256, SM_GEMM>>>(ah, al, wh, wl, hp, N);
    node_scores<<<N, 256>>>(hp, a1_src, a1_dst, ssrc, sdst, 4, 64);
    attn_agg<4, true><<<N, 128>>>(rowptr, srcs, ssrc, sdst, hp, nullptr, ah, al);

    // ---- layer 2 (H=1, F=256) ----
    split_f4<<<(n4w + 127) / 128, 128>>>(W2, wh, wl, n4w);
    gemm_bf16<<<gemm_grid, 256, SM_GEMM>>>(ah, al, wh, wl, hp, N);
    node_scores<<<N, 256>>>(hp, a2_src, a2_dst, ssrc, sdst, 1, 256);
    attn_agg<1, false><<<N, 128>>>(rowptr, srcs, ssrc, sdst, hp, out, nullptr, nullptr);
}

// round 6
// speedup vs baseline: 2.2395x; 1.1605x over previous
#include <cuda_runtime.h>
#include <cuda_bf16.h>
#include <cstdint>

#define NN 50000
#define EE 850000
#define DIM 256

// ---------------- scratch (device globals; no allocation allowed) -------------
__device__ float g_hp[NN * DIM];                 // GEMM output (fp32)
__device__ __nv_bfloat16 g_ah[NN * DIM];         // A operand hi (x split, then h)
__device__ __nv_bfloat16 g_al[NN * DIM];         // A operand lo
__device__ __nv_bfloat16 g_wh[DIM * DIM];        // W hi
__device__ __nv_bfloat16 g_wl[DIM * DIM];        // W lo
__device__ float g_ssrc[NN * 4];
__device__ float g_sdst[NN * 4];
__device__ float g_alpha[EE * 4];                // per-(edge-slot, head) exp values
__device__ float g_inv  [NN * 4];                // per-(node, head) 1/sum
__device__ int   g_cnt   [NN];
__device__ int   g_rowptr[NN + 1];
__device__ int   g_cursor[NN];
__device__ int   g_srcs  [EE];

// ======================= helpers =============================================
__device__ __forceinline__ uint32_t smem_u32(const void* p) {
    uint32_t a;
    asm("{ .reg .u64 t; cvta.to.shared.u64 t, %1; cvt.u32.u64 %0, t; }" : "=r"(a) : "l"(p));
    return a;
}
#define SW128(b) ((b) ^ (((b) >> 3) & 0x70))

struct Bf4 { uint2 hi, lo; };
__device__ __forceinline__ Bf4 split4(float4 v) {
    Bf4 r;
    __nv_bfloat16 h0 = __float2bfloat16(v.x), h1 = __float2bfloat16(v.y);
    __nv_bfloat16 h2 = __float2bfloat16(v.z), h3 = __float2bfloat16(v.w);
    __nv_bfloat16 l0 = __float2bfloat16(v.x - __bfloat162float(h0));
    __nv_bfloat16 l1 = __float2bfloat16(v.y - __bfloat162float(h1));
    __nv_bfloat16 l2 = __float2bfloat16(v.z - __bfloat162float(h2));
    __nv_bfloat16 l3 = __float2bfloat16(v.w - __bfloat162float(h3));
    r.hi.x = (uint32_t)__bfloat16_as_ushort(h0) | ((uint32_t)__bfloat16_as_ushort(h1) << 16);
    r.hi.y = (uint32_t)__bfloat16_as_ushort(h2) | ((uint32_t)__bfloat16_as_ushort(h3) << 16);
    r.lo.x = (uint32_t)__bfloat16_as_ushort(l0) | ((uint32_t)__bfloat16_as_ushort(l1) << 16);
    r.lo.y = (uint32_t)__bfloat16_as_ushort(l2) | ((uint32_t)__bfloat16_as_ushort(l3) << 16);
    return r;
}

#define LDSM_X4(r0, r1, r2, r3, a) \
    asm volatile("ldmatrix.sync.aligned.m8n8.x4.shared.b16 {%0,%1,%2,%3}, [%4];" \
        : "=r"(r0), "=r"(r1), "=r"(r2), "=r"(r3) : "r"(a))

#define MMA_16816(d, a, b0, b1) \
    asm volatile("mma.sync.aligned.m16n8k16.row.col.f32.bf16.bf16.f32 " \
        "{%0,%1,%2,%3}, {%4,%5,%6,%7}, {%8,%9}, {%0,%1,%2,%3};" \
        : "+f"((d)[0]), "+f"((d)[1]), "+f"((d)[2]), "+f"((d)[3]) \
        : "r"((a)[0]), "r"((a)[1]), "r"((a)[2]), "r"((a)[3]), "r"(b0), "r"(b1))

#define CP16(dst, src, sz) \
    asm volatile("cp.async.cg.shared.global [%0], [%1], 16, %2;" \
        :: "r"(dst), "l"(src), "r"(sz) : "memory")
#define CP_COMMIT() asm volatile("cp.async.commit_group;" ::: "memory")
#define CP_WAIT1() asm volatile("cp.async.wait_group 1;" ::: "memory")
#define CP_WAIT0() asm volatile("cp.async.wait_group 0;" ::: "memory")

// =================== fp32 -> bf16 hi/lo split (elementwise) ===================
__global__ void split_f4(const float* __restrict__ in, __nv_bfloat16* __restrict__ hi,
                         __nv_bfloat16* __restrict__ lo, int n4) {
    int i = blockIdx.x * blockDim.x + threadIdx.x;
    if (i >= n4) return;
    Bf4 s = split4(((const float4*)in)[i]);
    ((uint2*)hi)[i] = s.hi;
    ((uint2*)lo)[i] = s.lo;
}

// =================== HMMA bf16 split-3 GEMM (pre-split, cp.async pipelined) ===
static constexpr int BUF = 65536;
static constexpr int SM_GEMM = 2 * BUF + 1024;

__global__ __launch_bounds__(256)
void gemm_bf16(const __nv_bfloat16* __restrict__ Ah, const __nv_bfloat16* __restrict__ Al,
               const __nv_bfloat16* __restrict__ Bh, const __nv_bfloat16* __restrict__ Bl,
               float* __restrict__ C, int N) {
    extern __shared__ char smem_raw[];
    uint32_t sb0 = smem_u32(smem_raw);
    uint32_t sb  = (sb0 + 1023u) & ~1023u;

    const int tid  = threadIdx.x;
    const int lane = tid & 31;
    const int wid  = tid >> 5;
    const int n0 = blockIdx.x * 128;
    const int m0 = blockIdx.y * 128;
    const int m_warp = (wid >> 1) * 32;
    const int n_warp = (wid & 1) * 64;

    const char* pAh = (const char*)Ah;
    const char* pAl = (const char*)Al;
    const char* pBh = (const char*)Bh;
    const char* pBl = (const char*)Bl;

    auto load_chunk = [&](int c, int b) {
#pragma unroll
        for (int i = 0; i < 4; i++) {
            int idx = tid + 256 * i;
            int r   = idx >> 3;
            int k16 = (idx & 7) * 16;
            uint32_t off = SW128((uint32_t)(r * 128 + k16));
            uint32_t base = sb + b * BUF;
            int arow = n0 + r;
            int pa = (arow < N) ? 16 : 0;
            size_t ga = (size_t)min(arow, N - 1) * 512 + (size_t)c * 128 + k16;
            CP16(base + 0     + off, pAh + ga, pa);
            CP16(base + 16384 + off, pAl + ga, pa);
            size_t gb = (size_t)(m0 + r) * 512 + (size_t)c * 128 + k16;
            CP16(base + 32768 + off, pBh + gb, 16);
            CP16(base + 49152 + off, pBl + gb, 16);
        }
        CP_COMMIT();
    };

    float acc[2][8][4];
#pragma unroll
    for (int i = 0; i < 2; i++)
#pragma unroll
        for (int j = 0; j < 8; j++)
#pragma unroll
            for (int q = 0; q < 4; q++) acc[i][j][q] = 0.f;

    const int a_row = (lane & 15);
    const int a_khi = (lane >> 4) << 3;
    const int b_row = (lane & 7) + ((lane >> 4) << 3);
    const int b_khi = ((lane >> 3) & 1) << 3;

    load_chunk(0, 0);

    for (int c = 0; c < 4; c++) {
        if (c < 3) load_chunk(c + 1, (c + 1) & 1);
        if (c < 3) { CP_WAIT1(); } else { CP_WAIT0(); }
        __syncthreads();

        uint32_t base = sb + (c & 1) * BUF;
#pragma unroll
        for (int ks = 0; ks < 4; ks++) {
            int kb_a = ks * 16 + a_khi;
            int kb_b = ks * 16 + b_khi;

            uint32_t ah[2][4], bh[4][4];
#pragma unroll
            for (int mt = 0; mt < 2; mt++) {
                uint32_t ad = base + 0 +
                    SW128((uint32_t)((m_warp + mt * 16 + a_row) * 128 + kb_a * 2));
                LDSM_X4(ah[mt][0], ah[mt][1], ah[mt][2], ah[mt][3], ad);
            }
#pragma unroll
            for (int p = 0; p < 4; p++) {
                uint32_t bd = base + 32768 +
                    SW128((uint32_t)((n_warp + p * 16 + b_row) * 128 + kb_b * 2));
                LDSM_X4(bh[p][0], bh[p][1], bh[p][2], bh[p][3], bd);
            }
#pragma unroll
            for (int mt = 0; mt < 2; mt++)
#pragma unroll
                for (int p = 0; p < 4; p++) {
                    MMA_16816(acc[mt][p * 2 + 0], ah[mt], bh[p][0], bh[p][1]);
                    MMA_16816(acc[mt][p * 2 + 1], ah[mt], bh[p][2], bh[p][3]);
                }

            uint32_t bl[4][4];
#pragma unroll
            for (int p = 0; p < 4; p++) {
                uint32_t bd = base + 49152 +
                    SW128((uint32_t)((n_warp + p * 16 + b_row) * 128 + kb_b * 2));
                LDSM_X4(bl[p][0], bl[p][1], bl[p][2], bl[p][3], bd);
            }
#pragma unroll
            for (int mt = 0; mt < 2; mt++)
#pragma unroll
                for (int p = 0; p < 4; p++) {
                    MMA_16816(acc[mt][p * 2 + 0], ah[mt], bl[p][0], bl[p][1]);
                    MMA_16816(acc[mt][p * 2 + 1], ah[mt], bl[p][2], bl[p][3]);
                }

            uint32_t al[2][4];
#pragma unroll
            for (int mt = 0; mt < 2; mt++) {
                uint32_t ad = base + 16384 +
                    SW128((uint32_t)((m_warp + mt * 16 + a_row) * 128 + kb_a * 2));
                LDSM_X4(al[mt][0], al[mt][1], al[mt][2], al[mt][3], ad);
            }
#pragma unroll
            for (int mt = 0; mt < 2; mt++)
#pragma unroll
                for (int p = 0; p < 4; p++) {
                    MMA_16816(acc[mt][p * 2 + 0], al[mt], bh[p][0], bh[p][1]);
                    MMA_16816(acc[mt][p * 2 + 1], al[mt], bh[p][2], bh[p][3]);
                }
        }
        __syncthreads();
    }

#pragma unroll
    for (int mt = 0; mt < 2; mt++) {
        int row = n0 + m_warp + mt * 16 + (lane >> 2);
#pragma unroll
        for (int nt = 0; nt < 8; nt++) {
            int col = m0 + n_warp + nt * 8 + (lane & 3) * 2;
            if (row < N)
                *(float2*)(C + (size_t)row * 256 + col)
                    = make_float2(acc[mt][nt][0], acc[mt][nt][1]);
            if (row + 8 < N)
                *(float2*)(C + (size_t)(row + 8) * 256 + col)
                    = make_float2(acc[mt][nt][2], acc[mt][nt][3]);
        }
    }
}

// =================== per-node attention scores ================================
__global__ void node_scores(const float* __restrict__ hp,
                            const float* __restrict__ a_src,
                            const float* __restrict__ a_dst,
                            float* __restrict__ s_src, float* __restrict__ s_dst,
                            int Hh, int F) {
    int n = blockIdx.x;
    int t = threadIdx.x;
    float v = hp[(size_t)n * DIM + t];
    __shared__ float shs[DIM];
    __shared__ float shd[DIM];
    shs[t] = v * a_src[t];
    shd[t] = v * a_dst[t];
    __syncthreads();
    for (int st = F >> 1; st > 0; st >>= 1) {
        if ((t & (F - 1)) < st) { shs[t] += shs[t + st]; shd[t] += shd[t + st]; }
        __syncthreads();
    }
    if ((t & (F - 1)) == 0) {
        int h = t / F;
        s_src[(size_t)n * Hh + h] = shs[t];
        s_dst[(size_t)n * Hh + h] = shd[t];
    }
}

// =================== CSR build ================================================
__global__ void count_deg(const int* __restrict__ dst, int* __restrict__ cnt, int E) {
    int e = blockIdx.x * blockDim.x + threadIdx.x;
    if (e < E) atomicAdd(&cnt[dst[e]], 1);
}

__global__ void scan_rowptr(const int* __restrict__ cnt, int* __restrict__ rowptr,
                            int* __restrict__ cursor, int N) {
    __shared__ int part[1024];
    int t = threadIdx.x;
    int chunk = (N + 1023) / 1024;
    int b = t * chunk;
    int e = min(b + chunk, N);
    int s = 0;
    for (int i = b; i < e; i++) s += cnt[i];
    part[t] = s;
    __syncthreads();
    for (int off = 1; off < 1024; off <<= 1) {
        int v = (t >= off) ? part[t - off] : 0;
        __syncthreads();
        part[t] += v;
        __syncthreads();
    }
    int run = (t > 0) ? part[t - 1] : 0;
    for (int i = b; i < e; i++) {
        rowptr[i] = run;
        cursor[i] = run;
        run += cnt[i];
    }
    if (t == 1023) rowptr[N] = part[1023];
}

__global__ void scatter_edges(const int* __restrict__ src, const int* __restrict__ dst,
                              int* __restrict__ cursor, int* __restrict__ srcs, int E) {
    int e = blockIdx.x * blockDim.x + threadIdx.x;
    if (e < E) {
        int p = atomicAdd(&cursor[dst[e]], 1);
        srcs[p] = src[e];
    }
}

// =================== softmax alpha (warp per node) ============================
// Writes unnormalized exp to alpha[slot*H + h] and 1/sum to inv[n*H + h].
template <int H>
__global__ __launch_bounds__(256) void calc_alpha(
    const int* __restrict__ rowptr, const int* __restrict__ srcs,
    const float* __restrict__ ssrc, const float* __restrict__ sdst,
    float* __restrict__ alpha, float* __restrict__ inv, int N) {
    int warp = (blockIdx.x * blockDim.x + threadIdx.x) >> 5;
    int lane = threadIdx.x & 31;
    if (warp >= N) return;
    int n = warp;
    int beg = rowptr[n];
    int deg = rowptr[n + 1] - beg;

    float sd[H];
#pragma unroll
    for (int h = 0; h < H; h++) sd[h] = sdst[(size_t)n * H + h];

    // pass 1: max
    float m[H];
#pragma unroll
    for (int h = 0; h < H; h++) m[h] = -1e30f;
    for (int i = lane; i < deg; i += 32) {
        int s = srcs[beg + i];
#pragma unroll
        for (int h = 0; h < H; h++) {
            float v = ssrc[(size_t)s * H + h] + sd[h];
            v = v > 0.f ? v : 0.2f * v;
            m[h] = fmaxf(m[h], v);
        }
    }
#pragma unroll
    for (int o = 16; o > 0; o >>= 1)
#pragma unroll
        for (int h = 0; h < H; h++)
            m[h] = fmaxf(m[h], __shfl_xor_sync(0xffffffffu, m[h], o));

    // pass 2: exp + store + sum
    float sum[H];
#pragma unroll
    for (int h = 0; h < H; h++) sum[h] = 0.f;
    for (int i = lane; i < deg; i += 32) {
        int s = srcs[beg + i];
        float ex[H];
#pragma unroll
        for (int h = 0; h < H; h++) {
            float v = ssrc[(size_t)s * H + h] + sd[h];
            v = v > 0.f ? v : 0.2f * v;
            ex[h] = __expf(v - m[h]);
            sum[h] += ex[h];
        }
        if (H == 4)
            *(float4*)(alpha + (size_t)(beg + i) * 4)
                = make_float4(ex[0], ex[1], ex[2], ex[3]);
        else
            alpha[beg + i] = ex[0];
    }
#pragma unroll
    for (int o = 16; o > 0; o >>= 1)
#pragma unroll
        for (int h = 0; h < H; h++)
            sum[h] += __shfl_xor_sync(0xffffffffu, sum[h], o);

    if (lane < H) inv[(size_t)n * H + lane] = 1.0f / (sum[lane] + 1e-16f);
}

// =================== SpMM aggregation =========================================
// 64 threads per node; thread owns cols 4t..4t+3 (head = t/16 for H=4, 0 for H=1).
template <int H, bool SPLIT>
__global__ __launch_bounds__(64) void spmm_agg(
    const int* __restrict__ rowptr, const int* __restrict__ srcs,
    const float* __restrict__ alpha, const float* __restrict__ inv,
    const float* __restrict__ hp, float* __restrict__ out,
    __nv_bfloat16* __restrict__ oh, __nv_bfloat16* __restrict__ ol) {
    int n = blockIdx.x;
    int t = threadIdx.x;
    int beg = rowptr[n];
    int deg = rowptr[n + 1] - beg;
    int col = t * 4;
    int h = (H == 1) ? 0 : (t >> 4);

    float4 acc = make_float4(0.f, 0.f, 0.f, 0.f);

    int s_cur = srcs[beg];
    float a_cur = alpha[(size_t)beg * H + h];
    for (int i = 0; i < deg; i++) {
        int s_nxt = 0; float a_nxt = 0.f;
        if (i + 1 < deg) {
            s_nxt = srcs[beg + i + 1];
            a_nxt = alpha[(size_t)(beg + i + 1) * H + h];
        }
        float4 v = *(const float4*)(hp + (size_t)s_cur * DIM + col);
        acc.x += a_cur * v.x; acc.y += a_cur * v.y;
        acc.z += a_cur * v.z; acc.w += a_cur * v.w;
        s_cur = s_nxt; a_cur = a_nxt;
    }

    float iv = inv[(size_t)n * H + h];
    acc.x *= iv; acc.y *= iv; acc.z *= iv; acc.w *= iv;

    if (SPLIT) {
        acc.x = fmaxf(acc.x, 0.f); acc.y = fmaxf(acc.y, 0.f);
        acc.z = fmaxf(acc.z, 0.f); acc.w = fmaxf(acc.w, 0.f);
        Bf4 s = split4(acc);
        *(uint2*)((char*)oh + ((size_t)n * DIM + col) * 2) = s.hi;
        *(uint2*)((char*)ol + ((size_t)n * DIM + col) * 2) = s.lo;
    } else {
        *(float4*)(out + (size_t)n * DIM + col) = acc;
    }
}

// ==============================================================================
extern "C" void kernel_launch(void* const* d_in, const int* in_sizes, int n_in,
                              void* d_out, int out_size) {
    const float* x      = (const float*)d_in[0];
    const int*   ei     = (const int*)  d_in[1];
    const float* W1     = (const float*)d_in[2];
    const float* a1_src = (const float*)d_in[3];
    const float* a1_dst = (const float*)d_in[4];
    const float* W2     = (const float*)d_in[5];
    const float* a2_src = (const float*)d_in[6];
    const float* a2_dst = (const float*)d_in[7];

    int N = in_sizes[0] / DIM;
    int E = in_sizes[1] / 2;
    const int* src = ei;
    const int* dst = ei + E;

    float *hp, *ssrc, *sdst, *alpha, *inv;
    __nv_bfloat16 *ah, *al, *wh, *wl;
    int *cnt, *rowptr, *cursor, *srcs;
    cudaGetSymbolAddress((void**)&hp,     g_hp);
    cudaGetSymbolAddress((void**)&ah,     g_ah);
    cudaGetSymbolAddress((void**)&al,     g_al);
    cudaGetSymbolAddress((void**)&wh,     g_wh);
    cudaGetSymbolAddress((void**)&wl,     g_wl);
    cudaGetSymbolAddress((void**)&ssrc,   g_ssrc);
    cudaGetSymbolAddress((void**)&sdst,   g_sdst);
    cudaGetSymbolAddress((void**)&alpha,  g_alpha);
    cudaGetSymbolAddress((void**)&inv,    g_inv);
    cudaGetSymbolAddress((void**)&cnt,    g_cnt);
    cudaGetSymbolAddress((void**)&rowptr, g_rowptr);
    cudaGetSymbolAddress((void**)&cursor, g_cursor);
    cudaGetSymbolAddress((void**)&srcs,   g_srcs);

    float* out = (float*)d_out;

    cudaFuncSetAttribute(gemm_bf16, cudaFuncAttributeMaxDynamicSharedMemorySize, SM_GEMM);

    // ---- CSR build ----
    cudaMemsetAsync(cnt, 0, (size_t)N * sizeof(int));
    count_deg<<<(E + 255) / 256, 256>>>(dst, cnt, E);
    scan_rowptr<<<1, 1024>>>(cnt, rowptr, cursor, N);
    scatter_edges<<<(E + 255) / 256, 256>>>(src, dst, cursor, srcs, E);

    dim3 gemm_grid((N + 127) / 128, 2);
    int n4x = N * DIM / 4;
    int n4w = DIM * DIM / 4;
    int nwarp_grid = (N * 32 + 255) / 256;

    // ---- layer 1 (H=4, F=64) ----
    split_f4<<<(n4w + 127) / 128, 128>>>(W1, wh, wl, n4w);
    split_f4<<<(n4x + 127) / 128, 128>>>(x, ah, al, n4x);
    gemm_bf16<<<gemm_grid, 256, SM_GEMM>>>(ah, al, wh, wl, hp, N);
    node_scores<<<N, 256>>>(hp, a1_src, a1_dst, ssrc, sdst, 4, 64);
    calc_alpha<4><<<nwarp_grid, 256>>>(rowptr, srcs, ssrc, sdst, alpha, inv, N);
    spmm_agg<4, true><<<N, 64>>>(rowptr, srcs, alpha, inv, hp, nullptr, ah, al);

    // ---- layer 2 (H=1, F=256) ----
    split_f4<<<(n4w + 127) / 128, 128>>>(W2, wh, wl, n4w);
    gemm_bf16<<<gemm_grid, 256, SM_GEMM>>>(ah, al, wh, wl, hp, N);
    node_scores<<<N, 256>>>(hp, a2_src, a2_dst, ssrc, sdst, 1, 256);
    calc_alpha<1><<<nwarp_grid, 256>>>(rowptr, srcs, ssrc, sdst, alpha, inv, N);
    spmm_agg<1, false><<<N, 64>>>(rowptr, srcs, alpha, inv, hp, out, nullptr, nullptr);
}

// round 7
// speedup vs baseline: 3.2544x; 1.4531x over previous
#include <cuda_runtime.h>
#include <cuda_bf16.h>
#include <cstdint>

#define NN 50000
#define EE 850000
#define DIM 256

// ---------------- scratch (device globals; no allocation allowed) -------------
__device__ float g_hp[NN * DIM];                 // GEMM output (fp32)
__device__ __nv_bfloat16 g_ah[NN * DIM];         // A operand hi (x split, then h)
__device__ __nv_bfloat16 g_al[NN * DIM];         // A operand lo
__device__ __nv_bfloat16 g_wh[2 * DIM * DIM];    // W1|W2 hi
__device__ __nv_bfloat16 g_wl[2 * DIM * DIM];    // W1|W2 lo
__device__ float g_ssrc[NN * 4];
__device__ float g_sdst[NN * 4];
__device__ float g_alpha[EE * 4];                // per-(edge-slot, head) exp values
__device__ float g_inv  [NN * 4];                // per-(node, head) 1/sum
__device__ int   g_cnt   [NN];
__device__ int   g_rowptr[NN + 1];
__device__ int   g_cursor[NN];
__device__ int   g_srcs  [EE];

// ======================= helpers =============================================
__device__ __forceinline__ uint32_t smem_u32(const void* p) {
    uint32_t a;
    asm("{ .reg .u64 t; cvta.to.shared.u64 t, %1; cvt.u32.u64 %0, t; }" : "=r"(a) : "l"(p));
    return a;
}
#define SW128(b) ((b) ^ (((b) >> 3) & 0x70))

struct Bf4 { uint2 hi, lo; };
__device__ __forceinline__ Bf4 split4(float4 v) {
    Bf4 r;
    __nv_bfloat16 h0 = __float2bfloat16(v.x), h1 = __float2bfloat16(v.y);
    __nv_bfloat16 h2 = __float2bfloat16(v.z), h3 = __float2bfloat16(v.w);
    __nv_bfloat16 l0 = __float2bfloat16(v.x - __bfloat162float(h0));
    __nv_bfloat16 l1 = __float2bfloat16(v.y - __bfloat162float(h1));
    __nv_bfloat16 l2 = __float2bfloat16(v.z - __bfloat162float(h2));
    __nv_bfloat16 l3 = __float2bfloat16(v.w - __bfloat162float(h3));
    r.hi.x = (uint32_t)__bfloat16_as_ushort(h0) | ((uint32_t)__bfloat16_as_ushort(h1) << 16);
    r.hi.y = (uint32_t)__bfloat16_as_ushort(h2) | ((uint32_t)__bfloat16_as_ushort(h3) << 16);
    r.lo.x = (uint32_t)__bfloat16_as_ushort(l0) | ((uint32_t)__bfloat16_as_ushort(l1) << 16);
    r.lo.y = (uint32_t)__bfloat16_as_ushort(l2) | ((uint32_t)__bfloat16_as_ushort(l3) << 16);
    return r;
}

#define LDSM_X4(r0, r1, r2, r3, a) \
    asm volatile("ldmatrix.sync.aligned.m8n8.x4.shared.b16 {%0,%1,%2,%3}, [%4];" \
        : "=r"(r0), "=r"(r1), "=r"(r2), "=r"(r3) : "r"(a))

#define MMA_16816(d, a, b0, b1) \
    asm volatile("mma.sync.aligned.m16n8k16.row.col.f32.bf16.bf16.f32 " \
        "{%0,%1,%2,%3}, {%4,%5,%6,%7}, {%8,%9}, {%0,%1,%2,%3};" \
        : "+f"((d)[0]), "+f"((d)[1]), "+f"((d)[2]), "+f"((d)[3]) \
        : "r"((a)[0]), "r"((a)[1]), "r"((a)[2]), "r"((a)[3]), "r"(b0), "r"(b1))

#define CP16(dst, src, sz) \
    asm volatile("cp.async.cg.shared.global [%0], [%1], 16, %2;" \
        :: "r"(dst), "l"(src), "r"(sz) : "memory")
#define CP_COMMIT() asm volatile("cp.async.commit_group;" ::: "memory")
#define CP_WAIT1() asm volatile("cp.async.wait_group 1;" ::: "memory")
#define CP_WAIT0() asm volatile("cp.async.wait_group 0;" ::: "memory")

// =================== fp32 -> bf16 hi/lo split (elementwise) ===================
__global__ void split_f4(const float* __restrict__ in, __nv_bfloat16* __restrict__ hi,
                         __nv_bfloat16* __restrict__ lo, int n4) {
    int i = blockIdx.x * blockDim.x + threadIdx.x;
    if (i >= n4) return;
    Bf4 s = split4(((const float4*)in)[i]);
    ((uint2*)hi)[i] = s.hi;
    ((uint2*)lo)[i] = s.lo;
}

// =================== HMMA bf16 split-3 GEMM + fused attention scores ==========
// C[n][m] = sum_k A[n][k]*B[m][k]; also ssrc/sdst = hp . a_src/a_dst per head.
static constexpr int BUF = 65536;
static constexpr int SM_GEMM = 2 * BUF + 1024;

template <int H>
__global__ __launch_bounds__(256)
void gemm_bf16(const __nv_bfloat16* __restrict__ Ah, const __nv_bfloat16* __restrict__ Al,
               const __nv_bfloat16* __restrict__ Bh, const __nv_bfloat16* __restrict__ Bl,
               float* __restrict__ C, int N,
               const float* __restrict__ a_src, const float* __restrict__ a_dst,
               float* __restrict__ ssrc, float* __restrict__ sdst) {
    extern __shared__ char smem_raw[];
    uint32_t sb0 = smem_u32(smem_raw);
    uint32_t sb  = (sb0 + 1023u) & ~1023u;

    const int tid  = threadIdx.x;
    const int lane = tid & 31;
    const int wid  = tid >> 5;
    const int n0 = blockIdx.x * 128;
    const int m0 = blockIdx.y * 128;
    const int m_warp = (wid >> 1) * 32;
    const int n_warp = (wid & 1) * 64;

    const char* pAh = (const char*)Ah;
    const char* pAl = (const char*)Al;
    const char* pBh = (const char*)Bh;
    const char* pBl = (const char*)Bl;

    auto load_chunk = [&](int c, int b) {
#pragma unroll
        for (int i = 0; i < 4; i++) {
            int idx = tid + 256 * i;
            int r   = idx >> 3;
            int k16 = (idx & 7) * 16;
            uint32_t off = SW128((uint32_t)(r * 128 + k16));
            uint32_t base = sb + b * BUF;
            int arow = n0 + r;
            int pa = (arow < N) ? 16 : 0;
            size_t ga = (size_t)min(arow, N - 1) * 512 + (size_t)c * 128 + k16;
            CP16(base + 0     + off, pAh + ga, pa);
            CP16(base + 16384 + off, pAl + ga, pa);
            size_t gb = (size_t)(m0 + r) * 512 + (size_t)c * 128 + k16;
            CP16(base + 32768 + off, pBh + gb, 16);
            CP16(base + 49152 + off, pBl + gb, 16);
        }
        CP_COMMIT();
    };

    float acc[2][8][4];
#pragma unroll
    for (int i = 0; i < 2; i++)
#pragma unroll
        for (int j = 0; j < 8; j++)
#pragma unroll
            for (int q = 0; q < 4; q++) acc[i][j][q] = 0.f;

    const int a_row = (lane & 15);
    const int a_khi = (lane >> 4) << 3;
    const int b_row = (lane & 7) + ((lane >> 4) << 3);
    const int b_khi = ((lane >> 3) & 1) << 3;

    load_chunk(0, 0);

    for (int c = 0; c < 4; c++) {
        if (c < 3) load_chunk(c + 1, (c + 1) & 1);
        if (c < 3) { CP_WAIT1(); } else { CP_WAIT0(); }
        __syncthreads();

        uint32_t base = sb + (c & 1) * BUF;
#pragma unroll
        for (int ks = 0; ks < 4; ks++) {
            int kb_a = ks * 16 + a_khi;
            int kb_b = ks * 16 + b_khi;

            uint32_t ah[2][4], bh[4][4];
#pragma unroll
            for (int mt = 0; mt < 2; mt++) {
                uint32_t ad = base + 0 +
                    SW128((uint32_t)((m_warp + mt * 16 + a_row) * 128 + kb_a * 2));
                LDSM_X4(ah[mt][0], ah[mt][1], ah[mt][2], ah[mt][3], ad);
            }
#pragma unroll
            for (int p = 0; p < 4; p++) {
                uint32_t bd = base + 32768 +
                    SW128((uint32_t)((n_warp + p * 16 + b_row) * 128 + kb_b * 2));
                LDSM_X4(bh[p][0], bh[p][1], bh[p][2], bh[p][3], bd);
            }
#pragma unroll
            for (int mt = 0; mt < 2; mt++)
#pragma unroll
                for (int p = 0; p < 4; p++) {
                    MMA_16816(acc[mt][p * 2 + 0], ah[mt], bh[p][0], bh[p][1]);
                    MMA_16816(acc[mt][p * 2 + 1], ah[mt], bh[p][2], bh[p][3]);
                }

            uint32_t bl[4][4];
#pragma unroll
            for (int p = 0; p < 4; p++) {
                uint32_t bd = base + 49152 +
                    SW128((uint32_t)((n_warp + p * 16 + b_row) * 128 + kb_b * 2));
                LDSM_X4(bl[p][0], bl[p][1], bl[p][2], bl[p][3], bd);
            }
#pragma unroll
            for (int mt = 0; mt < 2; mt++)
#pragma unroll
                for (int p = 0; p < 4; p++) {
                    MMA_16816(acc[mt][p * 2 + 0], ah[mt], bl[p][0], bl[p][1]);
                    MMA_16816(acc[mt][p * 2 + 1], ah[mt], bl[p][2], bl[p][3]);
                }

            uint32_t al[2][4];
#pragma unroll
            for (int mt = 0; mt < 2; mt++) {
                uint32_t ad = base + 16384 +
                    SW128((uint32_t)((m_warp + mt * 16 + a_row) * 128 + kb_a * 2));
                LDSM_X4(al[mt][0], al[mt][1], al[mt][2], al[mt][3], ad);
            }
#pragma unroll
            for (int mt = 0; mt < 2; mt++)
#pragma unroll
                for (int p = 0; p < 4; p++) {
                    MMA_16816(acc[mt][p * 2 + 0], al[mt], bh[p][0], bh[p][1]);
                    MMA_16816(acc[mt][p * 2 + 1], al[mt], bh[p][2], bh[p][3]);
                }
        }
        __syncthreads();
    }

    // ---- load attention vectors for this warp's 64-col span ----
    float asv[16], adv[16];
#pragma unroll
    for (int nt = 0; nt < 8; nt++) {
        int col = m0 + n_warp + nt * 8 + (lane & 3) * 2;
        asv[nt * 2 + 0] = a_src[col]; asv[nt * 2 + 1] = a_src[col + 1];
        adv[nt * 2 + 0] = a_dst[col]; adv[nt * 2 + 1] = a_dst[col + 1];
    }

#pragma unroll
    for (int mt = 0; mt < 2; mt++) {
        int rowA = n0 + m_warp + mt * 16 + (lane >> 2);
        // C stores + per-row score partials
        float psA = 0.f, pdA = 0.f, psB = 0.f, pdB = 0.f;
#pragma unroll
        for (int nt = 0; nt < 8; nt++) {
            int col = m0 + n_warp + nt * 8 + (lane & 3) * 2;
            if (rowA < N)
                *(float2*)(C + (size_t)rowA * 256 + col)
                    = make_float2(acc[mt][nt][0], acc[mt][nt][1]);
            if (rowA + 8 < N)
                *(float2*)(C + (size_t)(rowA + 8) * 256 + col)
                    = make_float2(acc[mt][nt][2], acc[mt][nt][3]);
            psA += acc[mt][nt][0] * asv[nt * 2] + acc[mt][nt][1] * asv[nt * 2 + 1];
            pdA += acc[mt][nt][0] * adv[nt * 2] + acc[mt][nt][1] * adv[nt * 2 + 1];
            psB += acc[mt][nt][2] * asv[nt * 2] + acc[mt][nt][3] * asv[nt * 2 + 1];
            pdB += acc[mt][nt][2] * adv[nt * 2] + acc[mt][nt][3] * adv[nt * 2 + 1];
        }
#pragma unroll
        for (int o = 1; o <= 2; o <<= 1) {
            psA += __shfl_xor_sync(0xffffffffu, psA, o);
            pdA += __shfl_xor_sync(0xffffffffu, pdA, o);
            psB += __shfl_xor_sync(0xffffffffu, psB, o);
            pdB += __shfl_xor_sync(0xffffffffu, pdB, o);
        }
        if ((lane & 3) == 0) {
            int rowB = rowA + 8;
            if (H == 4) {
                int head = (m0 + n_warp) >> 6;
                if (rowA < N) { ssrc[(size_t)rowA * 4 + head] = psA; sdst[(size_t)rowA * 4 + head] = pdA; }
                if (rowB < N) { ssrc[(size_t)rowB * 4 + head] = psB; sdst[(size_t)rowB * 4 + head] = pdB; }
            } else {
                if (rowA < N) { atomicAdd(&ssrc[rowA], psA); atomicAdd(&sdst[rowA], pdA); }
                if (rowB < N) { atomicAdd(&ssrc[rowB], psB); atomicAdd(&sdst[rowB], pdB); }
            }
        }
    }
}

// =================== CSR build ================================================
__global__ void count_deg(const int* __restrict__ dst, int* __restrict__ cnt, int E) {
    int e = blockIdx.x * blockDim.x + threadIdx.x;
    if (e < E) atomicAdd(&cnt[dst[e]], 1);
}

__global__ void scan_rowptr(const int* __restrict__ cnt, int* __restrict__ rowptr,
                            int* __restrict__ cursor, int N) {
    __shared__ int part[1024];
    int t = threadIdx.x;
    int chunk = (N + 1023) / 1024;
    int b = t * chunk;
    int e = min(b + chunk, N);
    int s = 0;
    for (int i = b; i < e; i++) s += cnt[i];
    part[t] = s;
    __syncthreads();
    for (int off = 1; off < 1024; off <<= 1) {
        int v = (t >= off) ? part[t - off] : 0;
        __syncthreads();
        part[t] += v;
        __syncthreads();
    }
    int run = (t > 0) ? part[t - 1] : 0;
    for (int i = b; i < e; i++) {
        rowptr[i] = run;
        cursor[i] = run;
        run += cnt[i];
    }
    if (t == 1023) rowptr[N] = part[1023];
}

__global__ void scatter_edges(const int* __restrict__ src, const int* __restrict__ dst,
                              int* __restrict__ cursor, int* __restrict__ srcs, int E) {
    int e = blockIdx.x * blockDim.x + threadIdx.x;
    if (e < E) {
        int p = atomicAdd(&cursor[dst[e]], 1);
        srcs[p] = src[e];
    }
}

// =================== softmax alpha (warp per node) ============================
template <int H>
__global__ __launch_bounds__(256) void calc_alpha(
    const int* __restrict__ rowptr, const int* __restrict__ srcs,
    const float* __restrict__ ssrc, const float* __restrict__ sdst,
    float* __restrict__ alpha, float* __restrict__ inv, int N) {
    int warp = (blockIdx.x * blockDim.x + threadIdx.x) >> 5;
    int lane = threadIdx.x & 31;
    if (warp >= N) return;
    int n = warp;
    int beg = rowptr[n];
    int deg = rowptr[n + 1] - beg;

    float sd[H];
#pragma unroll
    for (int h = 0; h < H; h++) sd[h] = sdst[(size_t)n * H + h];

    float m[H];
#pragma unroll
    for (int h = 0; h < H; h++) m[h] = -1e30f;
    for (int i = lane; i < deg; i += 32) {
        int s = srcs[beg + i];
#pragma unroll
        for (int h = 0; h < H; h++) {
            float v = ssrc[(size_t)s * H + h] + sd[h];
            v = v > 0.f ? v : 0.2f * v;
            m[h] = fmaxf(m[h], v);
        }
    }
#pragma unroll
    for (int o = 16; o > 0; o >>= 1)
#pragma unroll
        for (int h = 0; h < H; h++)
            m[h] = fmaxf(m[h], __shfl_xor_sync(0xffffffffu, m[h], o));

    float sum[H];
#pragma unroll
    for (int h = 0; h < H; h++) sum[h] = 0.f;
    for (int i = lane; i < deg; i += 32) {
        int s = srcs[beg + i];
        float ex[H];
#pragma unroll
        for (int h = 0; h < H; h++) {
            float v = ssrc[(size_t)s * H + h] + sd[h];
            v = v > 0.f ? v : 0.2f * v;
            ex[h] = __expf(v - m[h]);
            sum[h] += ex[h];
        }
        if (H == 4)
            *(float4*)(alpha + (size_t)(beg + i) * 4)
                = make_float4(ex[0], ex[1], ex[2], ex[3]);
        else
            alpha[beg + i] = ex[0];
    }
#pragma unroll
    for (int o = 16; o > 0; o >>= 1)
#pragma unroll
        for (int h = 0; h < H; h++)
            sum[h] += __shfl_xor_sync(0xffffffffu, sum[h], o);

    if (lane < H) inv[(size_t)n * H + lane] = 1.0f / (sum[lane] + 1e-16f);
}

// =================== SpMM aggregation (pairwise edges for MLP) ================
template <int H, bool SPLIT>
__global__ __launch_bounds__(64) void spmm_agg(
    const int* __restrict__ rowptr, const int* __restrict__ srcs,
    const float* __restrict__ alpha, const float* __restrict__ inv,
    const float* __restrict__ hp, float* __restrict__ out,
    __nv_bfloat16* __restrict__ oh, __nv_bfloat16* __restrict__ ol) {
    int n = blockIdx.x;
    int t = threadIdx.x;
    int beg = rowptr[n];
    int deg = rowptr[n + 1] - beg;
    int col = t * 4;
    int h = (H == 1) ? 0 : (t >> 4);

    float4 acc = make_float4(0.f, 0.f, 0.f, 0.f);

    int i = 0;
    for (; i + 2 <= deg; i += 2) {
        int s0 = srcs[beg + i];
        int s1 = srcs[beg + i + 1];
        float a0 = alpha[(size_t)(beg + i) * H + h];
        float a1 = alpha[(size_t)(beg + i + 1) * H + h];
        float4 v0 = *(const float4*)(hp + (size_t)s0 * DIM + col);
        float4 v1 = *(const float4*)(hp + (size_t)s1 * DIM + col);
        acc.x += a0 * v0.x + a1 * v1.x;
        acc.y += a0 * v0.y + a1 * v1.y;
        acc.z += a0 * v0.z + a1 * v1.z;
        acc.w += a0 * v0.w + a1 * v1.w;
    }
    if (i < deg) {
        int s0 = srcs[beg + i];
        float a0 = alpha[(size_t)(beg + i) * H + h];
        float4 v0 = *(const float4*)(hp + (size_t)s0 * DIM + col);
        acc.x += a0 * v0.x; acc.y += a0 * v0.y;
        acc.z += a0 * v0.z; acc.w += a0 * v0.w;
    }

    float iv = inv[(size_t)n * H + h];
    acc.x *= iv; acc.y *= iv; acc.z *= iv; acc.w *= iv;

    if (SPLIT) {
        acc.x = fmaxf(acc.x, 0.f); acc.y = fmaxf(acc.y, 0.f);
        acc.z = fmaxf(acc.z, 0.f); acc.w = fmaxf(acc.w, 0.f);
        Bf4 s = split4(acc);
        *(uint2*)((char*)oh + ((size_t)n * DIM + col) * 2) = s.hi;
        *(uint2*)((char*)ol + ((size_t)n * DIM + col) * 2) = s.lo;
    } else {
        *(float4*)(out + (size_t)n * DIM + col) = acc;
    }
}

// ==============================================================================
extern "C" void kernel_launch(void* const* d_in, const int* in_sizes, int n_in,
                              void* d_out, int out_size) {
    const float* x      = (const float*)d_in[0];
    const int*   ei     = (const int*)  d_in[1];
    const float* W1     = (const float*)d_in[2];
    const float* a1_src = (const float*)d_in[3];
    const float* a1_dst = (const float*)d_in[4];
    const float* W2     = (const float*)d_in[5];
    const float* a2_src = (const float*)d_in[6];
    const float* a2_dst = (const float*)d_in[7];

    int N = in_sizes[0] / DIM;
    int E = in_sizes[1] / 2;
    const int* src = ei;
    const int* dst = ei + E;

    float *hp, *ssrc, *sdst, *alpha, *inv;
    __nv_bfloat16 *ah, *al, *wh, *wl;
    int *cnt, *rowptr, *cursor, *srcs;
    cudaGetSymbolAddress((void**)&hp,     g_hp);
    cudaGetSymbolAddress((void**)&ah,     g_ah);
    cudaGetSymbolAddress((void**)&al,     g_al);
    cudaGetSymbolAddress((void**)&wh,     g_wh);
    cudaGetSymbolAddress((void**)&wl,     g_wl);
    cudaGetSymbolAddress((void**)&ssrc,   g_ssrc);
    cudaGetSymbolAddress((void**)&sdst,   g_sdst);
    cudaGetSymbolAddress((void**)&alpha,  g_alpha);
    cudaGetSymbolAddress((void**)&inv,    g_inv);
    cudaGetSymbolAddress((void**)&cnt,    g_cnt);
    cudaGetSymbolAddress((void**)&rowptr, g_rowptr);
    cudaGetSymbolAddress((void**)&cursor, g_cursor);
    cudaGetSymbolAddress((void**)&srcs,   g_srcs);

    float* out = (float*)d_out;
    __nv_bfloat16* wh2 = wh + DIM * DIM;
    __nv_bfloat16* wl2 = wl + DIM * DIM;

    static cudaStream_t s2 = nullptr;
    static cudaEvent_t ev_fork = nullptr, ev_csr = nullptr;
    if (!s2) {
        cudaStreamCreate(&s2);
        cudaEventCreateWithFlags(&ev_fork, cudaEventDisableTiming);
        cudaEventCreateWithFlags(&ev_csr, cudaEventDisableTiming);
    }

    cudaFuncSetAttribute(gemm_bf16<4>, cudaFuncAttributeMaxDynamicSharedMemorySize, SM_GEMM);
    cudaFuncSetAttribute(gemm_bf16<1>, cudaFuncAttributeMaxDynamicSharedMemorySize, SM_GEMM);

    dim3 gemm_grid((N + 127) / 128, 2);
    int n4x = N * DIM / 4;
    int n4w = DIM * DIM / 4;
    int nwarp_grid = (N * 32 + 255) / 256;

    // ---- fork: CSR build on side stream ----
    cudaEventRecord(ev_fork, 0);
    cudaStreamWaitEvent(s2, ev_fork, 0);
    cudaMemsetAsync(cnt, 0, (size_t)N * sizeof(int), s2);
    count_deg<<<(E + 255) / 256, 256, 0, s2>>>(dst, cnt, E);
    scan_rowptr<<<1, 1024, 0, s2>>>(cnt, rowptr, cursor, N);
    scatter_edges<<<(E + 255) / 256, 256, 0, s2>>>(src, dst, cursor, srcs, E);
    cudaEventRecord(ev_csr, s2);

    // ---- main stream: splits + GEMM1 ----
    split_f4<<<(n4w + 127) / 128, 128>>>(W1, wh, wl, n4w);
    split_f4<<<(n4w + 127) / 128, 128>>>(W2, wh2, wl2, n4w);
    split_f4<<<(n4x + 127) / 128, 128>>>(x, ah, al, n4x);
    gemm_bf16<4><<<gemm_grid, 256, SM_GEMM>>>(ah, al, wh, wl, hp, N,
                                              a1_src, a1_dst, ssrc, sdst);

    // ---- join CSR, layer-1 softmax + SpMM ----
    cudaStreamWaitEvent(0, ev_csr, 0);
    calc_alpha<4><<<nwarp_grid, 256>>>(rowptr, srcs, ssrc, sdst, alpha, inv, N);
    spmm_agg<4, true><<<N, 64>>>(rowptr, srcs, alpha, inv, hp, nullptr, ah, al);

    // ---- layer 2 (H=1): zero score buffers, GEMM2 (atomic scores) ----
    cudaMemsetAsync(ssrc, 0, (size_t)N * sizeof(float));
    cudaMemsetAsync(sdst, 0, (size_t)N * sizeof(float));
    gemm_bf16<1><<<gemm_grid, 256, SM_GEMM>>>(ah, al, wh2, wl2, hp, N,
                                              a2_src, a2_dst, ssrc, sdst);
    calc_alpha<1><<<nwarp_grid, 256>>>(rowptr, srcs, ssrc, sdst, alpha, inv, N);
    spmm_agg<1, false><<<N, 64>>>(rowptr, srcs, alpha, inv, hp, out, nullptr, nullptr);
}

// round 8
// speedup vs baseline: 3.5563x; 1.0928x over previous
#include <cuda_runtime.h>
#include <cuda_bf16.h>
#include <cstdint>

#define NN 50000
#define EE 850000
#define DIM 256

// ---------------- scratch (device globals; no allocation allowed) -------------
__device__ float g_hp[NN * DIM];                 // GEMM output (fp32)
__device__ __nv_bfloat16 g_ah[NN * DIM];         // A operand hi (x split, then h)
__device__ __nv_bfloat16 g_al[NN * DIM];         // A operand lo
__device__ __nv_bfloat16 g_wh[2 * DIM * DIM];    // W1|W2 hi
__device__ __nv_bfloat16 g_wl[2 * DIM * DIM];    // W1|W2 lo
__device__ float g_ssrc[NN * 4];
__device__ float g_sdst[NN * 4];
__device__ float g_alpha[EE * 4];                // per-(edge-slot, head) exp values
__device__ float g_inv  [NN * 4];                // per-(node, head) 1/sum
__device__ int   g_cnt   [NN];
__device__ int   g_rowptr[NN + 1];
__device__ int   g_cursor[NN];
__device__ int   g_srcs  [EE];

// ======================= helpers =============================================
__device__ __forceinline__ uint32_t smem_u32(const void* p) {
    uint32_t a;
    asm("{ .reg .u64 t; cvta.to.shared.u64 t, %1; cvt.u32.u64 %0, t; }" : "=r"(a) : "l"(p));
    return a;
}
#define SW128(b) ((b) ^ (((b) >> 3) & 0x70))

struct Bf4 { uint2 hi, lo; };
__device__ __forceinline__ Bf4 split4(float4 v) {
    Bf4 r;
    __nv_bfloat16 h0 = __float2bfloat16(v.x), h1 = __float2bfloat16(v.y);
    __nv_bfloat16 h2 = __float2bfloat16(v.z), h3 = __float2bfloat16(v.w);
    __nv_bfloat16 l0 = __float2bfloat16(v.x - __bfloat162float(h0));
    __nv_bfloat16 l1 = __float2bfloat16(v.y - __bfloat162float(h1));
    __nv_bfloat16 l2 = __float2bfloat16(v.z - __bfloat162float(h2));
    __nv_bfloat16 l3 = __float2bfloat16(v.w - __bfloat162float(h3));
    r.hi.x = (uint32_t)__bfloat16_as_ushort(h0) | ((uint32_t)__bfloat16_as_ushort(h1) << 16);
    r.hi.y = (uint32_t)__bfloat16_as_ushort(h2) | ((uint32_t)__bfloat16_as_ushort(h3) << 16);
    r.lo.x = (uint32_t)__bfloat16_as_ushort(l0) | ((uint32_t)__bfloat16_as_ushort(l1) << 16);
    r.lo.y = (uint32_t)__bfloat16_as_ushort(l2) | ((uint32_t)__bfloat16_as_ushort(l3) << 16);
    return r;
}

#define LDSM_X4(r0, r1, r2, r3, a) \
    asm volatile("ldmatrix.sync.aligned.m8n8.x4.shared.b16 {%0,%1,%2,%3}, [%4];" \
        : "=r"(r0), "=r"(r1), "=r"(r2), "=r"(r3) : "r"(a))

#define MMA_16816(d, a, b0, b1) \
    asm volatile("mma.sync.aligned.m16n8k16.row.col.f32.bf16.bf16.f32 " \
        "{%0,%1,%2,%3}, {%4,%5,%6,%7}, {%8,%9}, {%0,%1,%2,%3};" \
        : "+f"((d)[0]), "+f"((d)[1]), "+f"((d)[2]), "+f"((d)[3]) \
        : "r"((a)[0]), "r"((a)[1]), "r"((a)[2]), "r"((a)[3]), "r"(b0), "r"(b1))

#define CP16(dst, src, sz) \
    asm volatile("cp.async.cg.shared.global [%0], [%1], 16, %2;" \
        :: "r"(dst), "l"(src), "r"(sz) : "memory")
#define CP_COMMIT() asm volatile("cp.async.commit_group;" ::: "memory")
#define CP_WAIT1() asm volatile("cp.async.wait_group 1;" ::: "memory")
#define CP_WAIT0() asm volatile("cp.async.wait_group 0;" ::: "memory")

// =================== fp32 -> bf16 hi/lo splits ================================
__global__ void split_f4(const float* __restrict__ in, __nv_bfloat16* __restrict__ hi,
                         __nv_bfloat16* __restrict__ lo, int n4) {
    int i = blockIdx.x * blockDim.x + threadIdx.x;
    if (i >= n4) return;
    Bf4 s = split4(((const float4*)in)[i]);
    ((uint2*)hi)[i] = s.hi;
    ((uint2*)lo)[i] = s.lo;
}

// both weight matrices in one launch (W1 -> [0,n4w), W2 -> [n4w, 2*n4w))
__global__ void split_w2(const float* __restrict__ W1, const float* __restrict__ W2,
                         __nv_bfloat16* __restrict__ hi, __nv_bfloat16* __restrict__ lo,
                         int n4w) {
    int i = blockIdx.x * blockDim.x + threadIdx.x;
    if (i >= 2 * n4w) return;
    const float4* src = (i < n4w) ? &((const float4*)W1)[i]
                                  : &((const float4*)W2)[i - n4w];
    Bf4 s = split4(*src);
    ((uint2*)hi)[i] = s.hi;
    ((uint2*)lo)[i] = s.lo;
}

// =================== HMMA bf16 split-3 GEMM + fused attention scores ==========
static constexpr int BUF = 65536;
static constexpr int SM_GEMM = 2 * BUF + 1024;

template <int H>
__global__ __launch_bounds__(256)
void gemm_bf16(const __nv_bfloat16* __restrict__ Ah, const __nv_bfloat16* __restrict__ Al,
               const __nv_bfloat16* __restrict__ Bh, const __nv_bfloat16* __restrict__ Bl,
               float* __restrict__ C, int N,
               const float* __restrict__ a_src, const float* __restrict__ a_dst,
               float* __restrict__ ssrc, float* __restrict__ sdst) {
    extern __shared__ char smem_raw[];
    uint32_t sb0 = smem_u32(smem_raw);
    uint32_t sb  = (sb0 + 1023u) & ~1023u;

    const int tid  = threadIdx.x;
    const int lane = tid & 31;
    const int wid  = tid >> 5;
    const int n0 = blockIdx.x * 128;
    const int m0 = blockIdx.y * 128;
    const int m_warp = (wid >> 1) * 32;
    const int n_warp = (wid & 1) * 64;

    const char* pAh = (const char*)Ah;
    const char* pAl = (const char*)Al;
    const char* pBh = (const char*)Bh;
    const char* pBl = (const char*)Bl;

    auto load_chunk = [&](int c, int b) {
#pragma unroll
        for (int i = 0; i < 4; i++) {
            int idx = tid + 256 * i;
            int r   = idx >> 3;
            int k16 = (idx & 7) * 16;
            uint32_t off = SW128((uint32_t)(r * 128 + k16));
            uint32_t base = sb + b * BUF;
            int arow = n0 + r;
            int pa = (arow < N) ? 16 : 0;
            size_t ga = (size_t)min(arow, N - 1) * 512 + (size_t)c * 128 + k16;
            CP16(base + 0     + off, pAh + ga, pa);
            CP16(base + 16384 + off, pAl + ga, pa);
            size_t gb = (size_t)(m0 + r) * 512 + (size_t)c * 128 + k16;
            CP16(base + 32768 + off, pBh + gb, 16);
            CP16(base + 49152 + off, pBl + gb, 16);
        }
        CP_COMMIT();
    };

    float acc[2][8][4];
#pragma unroll
    for (int i = 0; i < 2; i++)
#pragma unroll
        for (int j = 0; j < 8; j++)
#pragma unroll
            for (int q = 0; q < 4; q++) acc[i][j][q] = 0.f;

    const int a_row = (lane & 15);
    const int a_khi = (lane >> 4) << 3;
    const int b_row = (lane & 7) + ((lane >> 4) << 3);
    const int b_khi = ((lane >> 3) & 1) << 3;

    load_chunk(0, 0);

    for (int c = 0; c < 4; c++) {
        if (c < 3) load_chunk(c + 1, (c + 1) & 1);
        if (c < 3) { CP_WAIT1(); } else { CP_WAIT0(); }
        __syncthreads();

        uint32_t base = sb + (c & 1) * BUF;
#pragma unroll
        for (int ks = 0; ks < 4; ks++) {
            int kb_a = ks * 16 + a_khi;
            int kb_b = ks * 16 + b_khi;

            uint32_t ah[2][4], bh[4][4];
#pragma unroll
            for (int mt = 0; mt < 2; mt++) {
                uint32_t ad = base + 0 +
                    SW128((uint32_t)((m_warp + mt * 16 + a_row) * 128 + kb_a * 2));
                LDSM_X4(ah[mt][0], ah[mt][1], ah[mt][2], ah[mt][3], ad);
            }
#pragma unroll
            for (int p = 0; p < 4; p++) {
                uint32_t bd = base + 32768 +
                    SW128((uint32_t)((n_warp + p * 16 + b_row) * 128 + kb_b * 2));
                LDSM_X4(bh[p][0], bh[p][1], bh[p][2], bh[p][3], bd);
            }
#pragma unroll
            for (int mt = 0; mt < 2; mt++)
#pragma unroll
                for (int p = 0; p < 4; p++) {
                    MMA_16816(acc[mt][p * 2 + 0], ah[mt], bh[p][0], bh[p][1]);
                    MMA_16816(acc[mt][p * 2 + 1], ah[mt], bh[p][2], bh[p][3]);
                }

            uint32_t bl[4][4];
#pragma unroll
            for (int p = 0; p < 4; p++) {
                uint32_t bd = base + 49152 +
                    SW128((uint32_t)((n_warp + p * 16 + b_row) * 128 + kb_b * 2));
                LDSM_X4(bl[p][0], bl[p][1], bl[p][2], bl[p][3], bd);
            }
#pragma unroll
            for (int mt = 0; mt < 2; mt++)
#pragma unroll
                for (int p = 0; p < 4; p++) {
                    MMA_16816(acc[mt][p * 2 + 0], ah[mt], bl[p][0], bl[p][1]);
                    MMA_16816(acc[mt][p * 2 + 1], ah[mt], bl[p][2], bl[p][3]);
                }

            uint32_t al[2][4];
#pragma unroll
            for (int mt = 0; mt < 2; mt++) {
                uint32_t ad = base + 16384 +
                    SW128((uint32_t)((m_warp + mt * 16 + a_row) * 128 + kb_a * 2));
                LDSM_X4(al[mt][0], al[mt][1], al[mt][2], al[mt][3], ad);
            }
#pragma unroll
            for (int mt = 0; mt < 2; mt++)
#pragma unroll
                for (int p = 0; p < 4; p++) {
                    MMA_16816(acc[mt][p * 2 + 0], al[mt], bh[p][0], bh[p][1]);
                    MMA_16816(acc[mt][p * 2 + 1], al[mt], bh[p][2], bh[p][3]);
                }
        }
        __syncthreads();
    }

    float asv[16], adv[16];
#pragma unroll
    for (int nt = 0; nt < 8; nt++) {
        int col = m0 + n_warp + nt * 8 + (lane & 3) * 2;
        asv[nt * 2 + 0] = a_src[col]; asv[nt * 2 + 1] = a_src[col + 1];
        adv[nt * 2 + 0] = a_dst[col]; adv[nt * 2 + 1] = a_dst[col + 1];
    }

#pragma unroll
    for (int mt = 0; mt < 2; mt++) {
        int rowA = n0 + m_warp + mt * 16 + (lane >> 2);
        float psA = 0.f, pdA = 0.f, psB = 0.f, pdB = 0.f;
#pragma unroll
        for (int nt = 0; nt < 8; nt++) {
            int col = m0 + n_warp + nt * 8 + (lane & 3) * 2;
            if (rowA < N)
                *(float2*)(C + (size_t)rowA * 256 + col)
                    = make_float2(acc[mt][nt][0], acc[mt][nt][1]);
            if (rowA + 8 < N)
                *(float2*)(C + (size_t)(rowA + 8) * 256 + col)
                    = make_float2(acc[mt][nt][2], acc[mt][nt][3]);
            psA += acc[mt][nt][0] * asv[nt * 2] + acc[mt][nt][1] * asv[nt * 2 + 1];
            pdA += acc[mt][nt][0] * adv[nt * 2] + acc[mt][nt][1] * adv[nt * 2 + 1];
            psB += acc[mt][nt][2] * asv[nt * 2] + acc[mt][nt][3] * asv[nt * 2 + 1];
            pdB += acc[mt][nt][2] * adv[nt * 2] + acc[mt][nt][3] * adv[nt * 2 + 1];
        }
#pragma unroll
        for (int o = 1; o <= 2; o <<= 1) {
            psA += __shfl_xor_sync(0xffffffffu, psA, o);
            pdA += __shfl_xor_sync(0xffffffffu, pdA, o);
            psB += __shfl_xor_sync(0xffffffffu, psB, o);
            pdB += __shfl_xor_sync(0xffffffffu, pdB, o);
        }
        if ((lane & 3) == 0) {
            int rowB = rowA + 8;
            if (H == 4) {
                int head = (m0 + n_warp) >> 6;
                if (rowA < N) { ssrc[(size_t)rowA * 4 + head] = psA; sdst[(size_t)rowA * 4 + head] = pdA; }
                if (rowB < N) { ssrc[(size_t)rowB * 4 + head] = psB; sdst[(size_t)rowB * 4 + head] = pdB; }
            } else {
                if (rowA < N) { atomicAdd(&ssrc[rowA], psA); atomicAdd(&sdst[rowA], pdA); }
                if (rowB < N) { atomicAdd(&ssrc[rowB], psB); atomicAdd(&sdst[rowB], pdB); }
            }
        }
    }
}

// =================== CSR build ================================================
__global__ void count_deg(const int* __restrict__ dst, int* __restrict__ cnt, int E) {
    int e = blockIdx.x * blockDim.x + threadIdx.x;
    if (e < E) atomicAdd(&cnt[dst[e]], 1);
}

__global__ void scan_rowptr(const int* __restrict__ cnt, int* __restrict__ rowptr,
                            int* __restrict__ cursor, int N) {
    __shared__ int part[1024];
    int t = threadIdx.x;
    int chunk = (N + 1023) / 1024;
    int b = t * chunk;
    int e = min(b + chunk, N);
    int s = 0;
    for (int i = b; i < e; i++) s += cnt[i];
    part[t] = s;
    __syncthreads();
    for (int off = 1; off < 1024; off <<= 1) {
        int v = (t >= off) ? part[t - off] : 0;
        __syncthreads();
        part[t] += v;
        __syncthreads();
    }
    int run = (t > 0) ? part[t - 1] : 0;
    for (int i = b; i < e; i++) {
        rowptr[i] = run;
        cursor[i] = run;
        run += cnt[i];
    }
    if (t == 1023) rowptr[N] = part[1023];
}

__global__ void scatter_edges(const int* __restrict__ src, const int* __restrict__ dst,
                              int* __restrict__ cursor, int* __restrict__ srcs, int E) {
    int e = blockIdx.x * blockDim.x + threadIdx.x;
    if (e < E) {
        int p = atomicAdd(&cursor[dst[e]], 1);
        srcs[p] = src[e];
    }
}

// =================== softmax alpha (warp per node) ============================
template <int H>
__global__ __launch_bounds__(256) void calc_alpha(
    const int* __restrict__ rowptr, const int* __restrict__ srcs,
    const float* __restrict__ ssrc, const float* __restrict__ sdst,
    float* __restrict__ alpha, float* __restrict__ inv, int N) {
    int warp = (blockIdx.x * blockDim.x + threadIdx.x) >> 5;
    int lane = threadIdx.x & 31;
    if (warp >= N) return;
    int n = warp;
    int beg = rowptr[n];
    int deg = rowptr[n + 1] - beg;

    float sd[H];
#pragma unroll
    for (int h = 0; h < H; h++) sd[h] = sdst[(size_t)n * H + h];

    float m[H];
#pragma unroll
    for (int h = 0; h < H; h++) m[h] = -1e30f;
    for (int i = lane; i < deg; i += 32) {
        int s = srcs[beg + i];
#pragma unroll
        for (int h = 0; h < H; h++) {
            float v = ssrc[(size_t)s * H + h] + sd[h];
            v = v > 0.f ? v : 0.2f * v;
            m[h] = fmaxf(m[h], v);
        }
    }
#pragma unroll
    for (int o = 16; o > 0; o >>= 1)
#pragma unroll
        for (int h = 0; h < H; h++)
            m[h] = fmaxf(m[h], __shfl_xor_sync(0xffffffffu, m[h], o));

    float sum[H];
#pragma unroll
    for (int h = 0; h < H; h++) sum[h] = 0.f;
    for (int i = lane; i < deg; i += 32) {
        int s = srcs[beg + i];
        float ex[H];
#pragma unroll
        for (int h = 0; h < H; h++) {
            float v = ssrc[(size_t)s * H + h] + sd[h];
            v = v > 0.f ? v : 0.2f * v;
            ex[h] = __expf(v - m[h]);
            sum[h] += ex[h];
        }
        if (H == 4)
            *(float4*)(alpha + (size_t)(beg + i) * 4)
                = make_float4(ex[0], ex[1], ex[2], ex[3]);
        else
            alpha[beg + i] = ex[0];
    }
#pragma unroll
    for (int o = 16; o > 0; o >>= 1)
#pragma unroll
        for (int h = 0; h < H; h++)
            sum[h] += __shfl_xor_sync(0xffffffffu, sum[h], o);

    if (lane < H) inv[(size_t)n * H + lane] = 1.0f / (sum[lane] + 1e-16f);
}

// =================== SpMM aggregation (smem-staged indices) ====================
// 64 threads per node; thread owns cols 4t..4t+3. srcs+alpha staged in smem
// in chunks of 64 edges so the hot loop issues only the hp float4 LDG.
template <int H, bool SPLIT>
__global__ __launch_bounds__(64) void spmm_agg(
    const int* __restrict__ rowptr, const int* __restrict__ srcs,
    const float* __restrict__ alpha, const float* __restrict__ inv,
    const float* __restrict__ hp, float* __restrict__ out,
    __nv_bfloat16* __restrict__ oh, __nv_bfloat16* __restrict__ ol) {
    int n = blockIdx.x;
    int t = threadIdx.x;
    int beg = rowptr[n];
    int deg = rowptr[n + 1] - beg;
    int col = t * 4;
    int h = (H == 1) ? 0 : (t >> 4);

    __shared__ int   sh_s[64];
    __shared__ float sh_a[64 * H];

    float4 acc = make_float4(0.f, 0.f, 0.f, 0.f);

    for (int c0 = 0; c0 < deg; c0 += 64) {
        int cnt = min(64, deg - c0);
        if (t < cnt) {
            sh_s[t] = srcs[beg + c0 + t];
            if (H == 4) {
                float4 a4 = *(const float4*)(alpha + (size_t)(beg + c0 + t) * 4);
                *(float4*)(sh_a + t * 4) = a4;
            } else {
                sh_a[t] = alpha[beg + c0 + t];
            }
        }
        __syncthreads();
        int i = 0;
        for (; i + 2 <= cnt; i += 2) {
            int s0 = sh_s[i];
            int s1 = sh_s[i + 1];
            float a0 = sh_a[i * H + h];
            float a1 = sh_a[(i + 1) * H + h];
            float4 v0 = *(const float4*)(hp + (size_t)s0 * DIM + col);
            float4 v1 = *(const float4*)(hp + (size_t)s1 * DIM + col);
            acc.x += a0 * v0.x + a1 * v1.x;
            acc.y += a0 * v0.y + a1 * v1.y;
            acc.z += a0 * v0.z + a1 * v1.z;
            acc.w += a0 * v0.w + a1 * v1.w;
        }
        if (i < cnt) {
            int s0 = sh_s[i];
            float a0 = sh_a[i * H + h];
            float4 v0 = *(const float4*)(hp + (size_t)s0 * DIM + col);
            acc.x += a0 * v0.x; acc.y += a0 * v0.y;
            acc.z += a0 * v0.z; acc.w += a0 * v0.w;
        }
        __syncthreads();
    }

    float iv = inv[(size_t)n * H + h];
    acc.x *= iv; acc.y *= iv; acc.z *= iv; acc.w *= iv;

    if (SPLIT) {
        acc.x = fmaxf(acc.x, 0.f); acc.y = fmaxf(acc.y, 0.f);
        acc.z = fmaxf(acc.z, 0.f); acc.w = fmaxf(acc.w, 0.f);
        Bf4 s = split4(acc);
        *(uint2*)((char*)oh + ((size_t)n * DIM + col) * 2) = s.hi;
        *(uint2*)((char*)ol + ((size_t)n * DIM + col) * 2) = s.lo;
    } else {
        *(float4*)(out + (size_t)n * DIM + col) = acc;
    }
}

// ==============================================================================
extern "C" void kernel_launch(void* const* d_in, const int* in_sizes, int n_in,
                              void* d_out, int out_size) {
    const float* x      = (const float*)d_in[0];
    const int*   ei     = (const int*)  d_in[1];
    const float* W1     = (const float*)d_in[2];
    const float* a1_src = (const float*)d_in[3];
    const float* a1_dst = (const float*)d_in[4];
    const float* W2     = (const float*)d_in[5];
    const float* a2_src = (const float*)d_in[6];
    const float* a2_dst = (const float*)d_in[7];

    int N = in_sizes[0] / DIM;
    int E = in_sizes[1] / 2;
    const int* src = ei;
    const int* dst = ei + E;

    float *hp, *ssrc, *sdst, *alpha, *inv;
    __nv_bfloat16 *ah, *al, *wh, *wl;
    int *cnt, *rowptr, *cursor, *srcs;
    cudaGetSymbolAddress((void**)&hp,     g_hp);
    cudaGetSymbolAddress((void**)&ah,     g_ah);
    cudaGetSymbolAddress((void**)&al,     g_al);
    cudaGetSymbolAddress((void**)&wh,     g_wh);
    cudaGetSymbolAddress((void**)&wl,     g_wl);
    cudaGetSymbolAddress((void**)&ssrc,   g_ssrc);
    cudaGetSymbolAddress((void**)&sdst,   g_sdst);
    cudaGetSymbolAddress((void**)&alpha,  g_alpha);
    cudaGetSymbolAddress((void**)&inv,    g_inv);
    cudaGetSymbolAddress((void**)&cnt,    g_cnt);
    cudaGetSymbolAddress((void**)&rowptr, g_rowptr);
    cudaGetSymbolAddress((void**)&cursor, g_cursor);
    cudaGetSymbolAddress((void**)&srcs,   g_srcs);

    float* out = (float*)d_out;
    __nv_bfloat16* wh2 = wh + DIM * DIM;
    __nv_bfloat16* wl2 = wl + DIM * DIM;

    static cudaStream_t s2 = nullptr;
    static cudaEvent_t ev_fork = nullptr, ev_csr = nullptr;
    if (!s2) {
        cudaStreamCreate(&s2);
        cudaEventCreateWithFlags(&ev_fork, cudaEventDisableTiming);
        cudaEventCreateWithFlags(&ev_csr, cudaEventDisableTiming);
    }

    cudaFuncSetAttribute(gemm_bf16<4>, cudaFuncAttributeMaxDynamicSharedMemorySize, SM_GEMM);
    cudaFuncSetAttribute(gemm_bf16<1>, cudaFuncAttributeMaxDynamicSharedMemorySize, SM_GEMM);

    dim3 gemm_grid((N + 127) / 128, 2);
    int n4x = N * DIM / 4;
    int n4w = DIM * DIM / 4;
    int nwarp_grid = (N * 32 + 255) / 256;

    // ---- fork: CSR build on side stream ----
    cudaEventRecord(ev_fork, 0);
    cudaStreamWaitEvent(s2, ev_fork, 0);
    cudaMemsetAsync(cnt, 0, (size_t)N * sizeof(int), s2);
    count_deg<<<(E + 255) / 256, 256, 0, s2>>>(dst, cnt, E);
    scan_rowptr<<<1, 1024, 0, s2>>>(cnt, rowptr, cursor, N);
    scatter_edges<<<(E + 255) / 256, 256, 0, s2>>>(src, dst, cursor, srcs, E);
    cudaEventRecord(ev_csr, s2);

    // ---- main stream: splits + GEMM1 ----
    split_w2<<<(2 * n4w + 127) / 128, 128>>>(W1, W2, wh, wl, n4w);
    split_f4<<<(n4x + 127) / 128, 128>>>(x, ah, al, n4x);
    gemm_bf16<4><<<gemm_grid, 256, SM_GEMM>>>(ah, al, wh, wl, hp, N,
                                              a1_src, a1_dst, ssrc, sdst);

    // ---- join CSR, layer-1 softmax + SpMM ----
    cudaStreamWaitEvent(0, ev_csr, 0);
    calc_alpha<4><<<nwarp_grid, 256>>>(rowptr, srcs, ssrc, sdst, alpha, inv, N);
    spmm_agg<4, true><<<N, 64>>>(rowptr, srcs, alpha, inv, hp, nullptr, ah, al);

    // ---- layer 2 (H=1) ----
    cudaMemsetAsync(ssrc, 0, (size_t)N * sizeof(float));
    cudaMemsetAsync(sdst, 0, (size_t)N * sizeof(float));
    gemm_bf16<1><<<gemm_grid, 256, SM_GEMM>>>(ah, al, wh2, wl2, hp, N,
                                              a2_src, a2_dst, ssrc, sdst);
    calc_alpha<1><<<nwarp_grid, 256>>>(rowptr, srcs, ssrc, sdst, alpha, inv, N);
    spmm_agg<1, false><<<N, 64>>>(rowptr, srcs, alpha, inv, hp, out, nullptr, nullptr);
}

// round 9
// speedup vs baseline: 3.6512x; 1.0267x over previous
#include <cuda_runtime.h>
#include <cuda_bf16.h>
#include <cstdint>

#define NN 50000
#define EE 850000
#define DIM 256

// ---------------- scratch (device globals; no allocation allowed) -------------
__device__ float g_hp[NN * DIM];                 // GEMM output (fp32)
__device__ __nv_bfloat16 g_ah[NN * DIM];         // A operand hi (x split, then h)
__device__ __nv_bfloat16 g_al[NN * DIM];         // A operand lo
__device__ __nv_bfloat16 g_wh[2 * DIM * DIM];    // W1|W2 hi
__device__ __nv_bfloat16 g_wl[2 * DIM * DIM];    // W1|W2 lo
__device__ float g_ssrc[NN * 4];
__device__ float g_sdst[NN * 4];
__device__ float g_alpha[EE * 4];                // per-(edge-slot, head) exp values
__device__ float g_inv  [NN * 4];                // per-(node, head) 1/sum
__device__ int   g_cnt   [NN];
__device__ int   g_rowptr[NN + 1];
__device__ int   g_cursor[NN];
__device__ int   g_srcs  [EE];

// ======================= helpers =============================================
__device__ __forceinline__ uint32_t smem_u32(const void* p) {
    uint32_t a;
    asm("{ .reg .u64 t; cvta.to.shared.u64 t, %1; cvt.u32.u64 %0, t; }" : "=r"(a) : "l"(p));
    return a;
}
#define SW128(b) ((b) ^ (((b) >> 3) & 0x70))

struct Bf4 { uint2 hi, lo; };
__device__ __forceinline__ Bf4 split4(float4 v) {
    Bf4 r;
    __nv_bfloat16 h0 = __float2bfloat16(v.x), h1 = __float2bfloat16(v.y);
    __nv_bfloat16 h2 = __float2bfloat16(v.z), h3 = __float2bfloat16(v.w);
    __nv_bfloat16 l0 = __float2bfloat16(v.x - __bfloat162float(h0));
    __nv_bfloat16 l1 = __float2bfloat16(v.y - __bfloat162float(h1));
    __nv_bfloat16 l2 = __float2bfloat16(v.z - __bfloat162float(h2));
    __nv_bfloat16 l3 = __float2bfloat16(v.w - __bfloat162float(h3));
    r.hi.x = (uint32_t)__bfloat16_as_ushort(h0) | ((uint32_t)__bfloat16_as_ushort(h1) << 16);
    r.hi.y = (uint32_t)__bfloat16_as_ushort(h2) | ((uint32_t)__bfloat16_as_ushort(h3) << 16);
    r.lo.x = (uint32_t)__bfloat16_as_ushort(l0) | ((uint32_t)__bfloat16_as_ushort(l1) << 16);
    r.lo.y = (uint32_t)__bfloat16_as_ushort(l2) | ((uint32_t)__bfloat16_as_ushort(l3) << 16);
    return r;
}

#define LDSM_X4(r0, r1, r2, r3, a) \
    asm volatile("ldmatrix.sync.aligned.m8n8.x4.shared.b16 {%0,%1,%2,%3}, [%4];" \
        : "=r"(r0), "=r"(r1), "=r"(r2), "=r"(r3) : "r"(a))

#define MMA_16816(d, a, b0, b1) \
    asm volatile("mma.sync.aligned.m16n8k16.row.col.f32.bf16.bf16.f32 " \
        "{%0,%1,%2,%3}, {%4,%5,%6,%7}, {%8,%9}, {%0,%1,%2,%3};" \
        : "+f"((d)[0]), "+f"((d)[1]), "+f"((d)[2]), "+f"((d)[3]) \
        : "r"((a)[0]), "r"((a)[1]), "r"((a)[2]), "r"((a)[3]), "r"(b0), "r"(b1))

#define CP16(dst, src, sz) \
    asm volatile("cp.async.cg.shared.global [%0], [%1], 16, %2;" \
        :: "r"(dst), "l"(src), "r"(sz) : "memory")
#define CP_COMMIT() asm volatile("cp.async.commit_group;" ::: "memory")
#define CP_WAIT1() asm volatile("cp.async.wait_group 1;" ::: "memory")
#define CP_WAIT0() asm volatile("cp.async.wait_group 0;" ::: "memory")

// =================== fp32 -> bf16 hi/lo splits ================================
__global__ void split_f4(const float* __restrict__ in, __nv_bfloat16* __restrict__ hi,
                         __nv_bfloat16* __restrict__ lo, int n4) {
    int i = blockIdx.x * blockDim.x + threadIdx.x;
    if (i >= n4) return;
    Bf4 s = split4(((const float4*)in)[i]);
    ((uint2*)hi)[i] = s.hi;
    ((uint2*)lo)[i] = s.lo;
}

__global__ void split_w2(const float* __restrict__ W1, const float* __restrict__ W2,
                         __nv_bfloat16* __restrict__ hi, __nv_bfloat16* __restrict__ lo,
                         int n4w) {
    int i = blockIdx.x * blockDim.x + threadIdx.x;
    if (i >= 2 * n4w) return;
    const float4* src = (i < n4w) ? &((const float4*)W1)[i]
                                  : &((const float4*)W2)[i - n4w];
    Bf4 s = split4(*src);
    ((uint2*)hi)[i] = s.hi;
    ((uint2*)lo)[i] = s.lo;
}

// =================== HMMA bf16 split-3 GEMM + fused attention scores ==========
// CTA tile 128(A rows) x 64(B rows); warp tile 32x32 (4x2 warps); 2 CTAs/SM.
// Stage: AH 16K | AL 16K | BH 8K | BL 8K = 48K; double-buffered.
static constexpr int STG = 49152;
static constexpr int SM_GEMM = 2 * STG + 1024;

template <int H>
__global__ __launch_bounds__(256, 2)
void gemm_bf16(const __nv_bfloat16* __restrict__ Ah, const __nv_bfloat16* __restrict__ Al,
               const __nv_bfloat16* __restrict__ Bh, const __nv_bfloat16* __restrict__ Bl,
               float* __restrict__ C, int N,
               const float* __restrict__ a_src, const float* __restrict__ a_dst,
               float* __restrict__ ssrc, float* __restrict__ sdst) {
    extern __shared__ char smem_raw[];
    uint32_t sb0 = smem_u32(smem_raw);
    uint32_t sb  = (sb0 + 1023u) & ~1023u;

    const int tid  = threadIdx.x;
    const int lane = tid & 31;
    const int wid  = tid >> 5;
    const int n0 = blockIdx.x * 128;          // A row block
    const int m0 = blockIdx.y * 64;           // B row (output col) block
    const int m_warp = (wid >> 1) * 32;
    const int n_warp = (wid & 1) * 32;

    const char* pAh = (const char*)Ah;
    const char* pAl = (const char*)Al;
    const char* pBh = (const char*)Bh;
    const char* pBl = (const char*)Bl;

    auto load_chunk = [&](int c, int b) {
        uint32_t base = sb + b * STG;
#pragma unroll
        for (int i = 0; i < 4; i++) {               // A: 1024 16B ops
            int idx = tid + 256 * i;
            int r   = idx >> 3;
            int k16 = (idx & 7) * 16;
            uint32_t off = SW128((uint32_t)(r * 128 + k16));
            int arow = n0 + r;
            int pa = (arow < N) ? 16 : 0;
            size_t ga = (size_t)min(arow, N - 1) * 512 + (size_t)c * 128 + k16;
            CP16(base + 0     + off, pAh + ga, pa);
            CP16(base + 16384 + off, pAl + ga, pa);
        }
#pragma unroll
        for (int i = 0; i < 2; i++) {               // B: 512 16B ops
            int idx = tid + 256 * i;
            int r   = idx >> 3;
            int k16 = (idx & 7) * 16;
            uint32_t off = SW128((uint32_t)(r * 128 + k16));
            size_t gb = (size_t)(m0 + r) * 512 + (size_t)c * 128 + k16;
            CP16(base + 32768 + off, pBh + gb, 16);
            CP16(base + 40960 + off, pBl + gb, 16);
        }
        CP_COMMIT();
    };

    float acc[2][4][4];
#pragma unroll
    for (int i = 0; i < 2; i++)
#pragma unroll
        for (int j = 0; j < 4; j++)
#pragma unroll
            for (int q = 0; q < 4; q++) acc[i][j][q] = 0.f;

    const int a_row = (lane & 15);
    const int a_khi = (lane >> 4) << 3;
    const int b_row = (lane & 7) + ((lane >> 4) << 3);
    const int b_khi = ((lane >> 3) & 1) << 3;

    load_chunk(0, 0);

    for (int c = 0; c < 4; c++) {
        if (c < 3) load_chunk(c + 1, (c + 1) & 1);
        if (c < 3) { CP_WAIT1(); } else { CP_WAIT0(); }
        __syncthreads();

        uint32_t base = sb + (c & 1) * STG;
#pragma unroll
        for (int ks = 0; ks < 4; ks++) {
            int kb_a = ks * 16 + a_khi;
            int kb_b = ks * 16 + b_khi;

            uint32_t ah[2][4], al[2][4], bh[2][4], bl[2][4];
#pragma unroll
            for (int mt = 0; mt < 2; mt++) {
                uint32_t off = SW128((uint32_t)((m_warp + mt * 16 + a_row) * 128 + kb_a * 2));
                LDSM_X4(ah[mt][0], ah[mt][1], ah[mt][2], ah[mt][3], base + 0 + off);
                LDSM_X4(al[mt][0], al[mt][1], al[mt][2], al[mt][3], base + 16384 + off);
            }
#pragma unroll
            for (int p = 0; p < 2; p++) {
                uint32_t off = SW128((uint32_t)((n_warp + p * 16 + b_row) * 128 + kb_b * 2));
                LDSM_X4(bh[p][0], bh[p][1], bh[p][2], bh[p][3], base + 32768 + off);
                LDSM_X4(bl[p][0], bl[p][1], bl[p][2], bl[p][3], base + 40960 + off);
            }
#pragma unroll
            for (int mt = 0; mt < 2; mt++)
#pragma unroll
                for (int p = 0; p < 2; p++) {
                    MMA_16816(acc[mt][p * 2 + 0], ah[mt], bh[p][0], bh[p][1]);
                    MMA_16816(acc[mt][p * 2 + 1], ah[mt], bh[p][2], bh[p][3]);
                    MMA_16816(acc[mt][p * 2 + 0], ah[mt], bl[p][0], bl[p][1]);
                    MMA_16816(acc[mt][p * 2 + 1], ah[mt], bl[p][2], bl[p][3]);
                    MMA_16816(acc[mt][p * 2 + 0], al[mt], bh[p][0], bh[p][1]);
                    MMA_16816(acc[mt][p * 2 + 1], al[mt], bh[p][2], bh[p][3]);
                }
        }
        __syncthreads();
    }

    // ---- epilogue: C stores + fused per-head score partials (atomicAdd) ----
    float asv[8], adv[8];
#pragma unroll
    for (int nt = 0; nt < 4; nt++) {
        int col = m0 + n_warp + nt * 8 + (lane & 3) * 2;
        asv[nt * 2 + 0] = a_src[col]; asv[nt * 2 + 1] = a_src[col + 1];
        adv[nt * 2 + 0] = a_dst[col]; adv[nt * 2 + 1] = a_dst[col + 1];
    }

#pragma unroll
    for (int mt = 0; mt < 2; mt++) {
        int rowA = n0 + m_warp + mt * 16 + (lane >> 2);
        float psA = 0.f, pdA = 0.f, psB = 0.f, pdB = 0.f;
#pragma unroll
        for (int nt = 0; nt < 4; nt++) {
            int col = m0 + n_warp + nt * 8 + (lane & 3) * 2;
            if (rowA < N)
                *(float2*)(C + (size_t)rowA * 256 + col)
                    = make_float2(acc[mt][nt][0], acc[mt][nt][1]);
            if (rowA + 8 < N)
                *(float2*)(C + (size_t)(rowA + 8) * 256 + col)
                    = make_float2(acc[mt][nt][2], acc[mt][nt][3]);
            psA += acc[mt][nt][0] * asv[nt * 2] + acc[mt][nt][1] * asv[nt * 2 + 1];
            pdA += acc[mt][nt][0] * adv[nt * 2] + acc[mt][nt][1] * adv[nt * 2 + 1];
            psB += acc[mt][nt][2] * asv[nt * 2] + acc[mt][nt][3] * asv[nt * 2 + 1];
            pdB += acc[mt][nt][2] * adv[nt * 2] + acc[mt][nt][3] * adv[nt * 2 + 1];
        }
#pragma unroll
        for (int o = 1; o <= 2; o <<= 1) {
            psA += __shfl_xor_sync(0xffffffffu, psA, o);
            pdA += __shfl_xor_sync(0xffffffffu, pdA, o);
            psB += __shfl_xor_sync(0xffffffffu, psB, o);
            pdB += __shfl_xor_sync(0xffffffffu, pdB, o);
        }
        if ((lane & 3) == 0) {
            int rowB = rowA + 8;
            if (H == 4) {
                int head = blockIdx.y;     // 64 cols per head, 64-col CTA tile
                if (rowA < N) { atomicAdd(&ssrc[(size_t)rowA * 4 + head], psA);
                                atomicAdd(&sdst[(size_t)rowA * 4 + head], pdA); }
                if (rowB < N) { atomicAdd(&ssrc[(size_t)rowB * 4 + head], psB);
                                atomicAdd(&sdst[(size_t)rowB * 4 + head], pdB); }
            } else {
                if (rowA < N) { atomicAdd(&ssrc[rowA], psA); atomicAdd(&sdst[rowA], pdA); }
                if (rowB < N) { atomicAdd(&ssrc[rowB], psB); atomicAdd(&sdst[rowB], pdB); }
            }
        }
    }
}

// =================== CSR build ================================================
__global__ void count_deg(const int* __restrict__ dst, int* __restrict__ cnt, int E) {
    int e = blockIdx.x * blockDim.x + threadIdx.x;
    if (e < E) atomicAdd(&cnt[dst[e]], 1);
}

__global__ void scan_rowptr(const int* __restrict__ cnt, int* __restrict__ rowptr,
                            int* __restrict__ cursor, int N) {
    __shared__ int part[1024];
    int t = threadIdx.x;
    int chunk = (N + 1023) / 1024;
    int b = t * chunk;
    int e = min(b + chunk, N);
    int s = 0;
    for (int i = b; i < e; i++) s += cnt[i];
    part[t] = s;
    __syncthreads();
    for (int off = 1; off < 1024; off <<= 1) {
        int v = (t >= off) ? part[t - off] : 0;
        __syncthreads();
        part[t] += v;
        __syncthreads();
    }
    int run = (t > 0) ? part[t - 1] : 0;
    for (int i = b; i < e; i++) {
        rowptr[i] = run;
        cursor[i] = run;
        run += cnt[i];
    }
    if (t == 1023) rowptr[N] = part[1023];
}

__global__ void scatter_edges(const int* __restrict__ src, const int* __restrict__ dst,
                              int* __restrict__ cursor, int* __restrict__ srcs, int E) {
    int e = blockIdx.x * blockDim.x + threadIdx.x;
    if (e < E) {
        int p = atomicAdd(&cursor[dst[e]], 1);
        srcs[p] = src[e];
    }
}

// =================== softmax alpha (warp per node) ============================
template <int H>
__global__ __launch_bounds__(256) void calc_alpha(
    const int* __restrict__ rowptr, const int* __restrict__ srcs,
    const float* __restrict__ ssrc, const float* __restrict__ sdst,
    float* __restrict__ alpha, float* __restrict__ inv, int N) {
    int warp = (blockIdx.x * blockDim.x + threadIdx.x) >> 5;
    int lane = threadIdx.x & 31;
    if (warp >= N) return;
    int n = warp;
    int beg = rowptr[n];
    int deg = rowptr[n + 1] - beg;

    float sd[H];
#pragma unroll
    for (int h = 0; h < H; h++) sd[h] = sdst[(size_t)n * H + h];

    float m[H];
#pragma unroll
    for (int h = 0; h < H; h++) m[h] = -1e30f;
    for (int i = lane; i < deg; i += 32) {
        int s = srcs[beg + i];
#pragma unroll
        for (int h = 0; h < H; h++) {
            float v = ssrc[(size_t)s * H + h] + sd[h];
            v = v > 0.f ? v : 0.2f * v;
            m[h] = fmaxf(m[h], v);
        }
    }
#pragma unroll
    for (int o = 16; o > 0; o >>= 1)
#pragma unroll
        for (int h = 0; h < H; h++)
            m[h] = fmaxf(m[h], __shfl_xor_sync(0xffffffffu, m[h], o));

    float sum[H];
#pragma unroll
    for (int h = 0; h < H; h++) sum[h] = 0.f;
    for (int i = lane; i < deg; i += 32) {
        int s = srcs[beg + i];
        float ex[H];
#pragma unroll
        for (int h = 0; h < H; h++) {
            float v = ssrc[(size_t)s * H + h] + sd[h];
            v = v > 0.f ? v : 0.2f * v;
            ex[h] = __expf(v - m[h]);
            sum[h] += ex[h];
        }
        if (H == 4)
            *(float4*)(alpha + (size_t)(beg + i) * 4)
                = make_float4(ex[0], ex[1], ex[2], ex[3]);
        else
            alpha[beg + i] = ex[0];
    }
#pragma unroll
    for (int o = 16; o > 0; o >>= 1)
#pragma unroll
        for (int h = 0; h < H; h++)
            sum[h] += __shfl_xor_sync(0xffffffffu, sum[h], o);

    if (lane < H) inv[(size_t)n * H + lane] = 1.0f / (sum[lane] + 1e-16f);
}

// =================== SpMM aggregation (smem-staged indices) ====================
template <int H, bool SPLIT>
__global__ __launch_bounds__(64) void spmm_agg(
    const int* __restrict__ rowptr, const int* __restrict__ srcs,
    const float* __restrict__ alpha, const float* __restrict__ inv,
    const float* __restrict__ hp, float* __restrict__ out,
    __nv_bfloat16* __restrict__ oh, __nv_bfloat16* __restrict__ ol) {
    int n = blockIdx.x;
    int t = threadIdx.x;
    int beg = rowptr[n];
    int deg = rowptr[n + 1] - beg;
    int col = t * 4;
    int h = (H == 1) ? 0 : (t >> 4);

    __shared__ int   sh_s[64];
    __shared__ float sh_a[64 * H];

    float4 acc = make_float4(0.f, 0.f, 0.f, 0.f);

    for (int c0 = 0; c0 < deg; c0 += 64) {
        int cnt = min(64, deg - c0);
        if (t < cnt) {
            sh_s[t] = srcs[beg + c0 + t];
            if (H == 4) {
                float4 a4 = *(const float4*)(alpha + (size_t)(beg + c0 + t) * 4);
                *(float4*)(sh_a + t * 4) = a4;
            } else {
                sh_a[t] = alpha[beg + c0 + t];
            }
        }
        __syncthreads();
        int i = 0;
        for (; i + 2 <= cnt; i += 2) {
            int s0 = sh_s[i];
            int s1 = sh_s[i + 1];
            float a0 = sh_a[i * H + h];
            float a1 = sh_a[(i + 1) * H + h];
            float4 v0 = *(const float4*)(hp + (size_t)s0 * DIM + col);
            float4 v1 = *(const float4*)(hp + (size_t)s1 * DIM + col);
            acc.x += a0 * v0.x + a1 * v1.x;
            acc.y += a0 * v0.y + a1 * v1.y;
            acc.z += a0 * v0.z + a1 * v1.z;
            acc.w += a0 * v0.w + a1 * v1.w;
        }
        if (i < cnt) {
            int s0 = sh_s[i];
            float a0 = sh_a[i * H + h];
            float4 v0 = *(const float4*)(hp + (size_t)s0 * DIM + col);
            acc.x += a0 * v0.x; acc.y += a0 * v0.y;
            acc.z += a0 * v0.z; acc.w += a0 * v0.w;
        }
        __syncthreads();
    }

    float iv = inv[(size_t)n * H + h];
    acc.x *= iv; acc.y *= iv; acc.z *= iv; acc.w *= iv;

    if (SPLIT) {
        acc.x = fmaxf(acc.x, 0.f); acc.y = fmaxf(acc.y, 0.f);
        acc.z = fmaxf(acc.z, 0.f); acc.w = fmaxf(acc.w, 0.f);
        Bf4 s = split4(acc);
        *(uint2*)((char*)oh + ((size_t)n * DIM + col) * 2) = s.hi;
        *(uint2*)((char*)ol + ((size_t)n * DIM + col) * 2) = s.lo;
    } else {
        *(float4*)(out + (size_t)n * DIM + col) = acc;
    }
}

// ==============================================================================
extern "C" void kernel_launch(void* const* d_in, const int* in_sizes, int n_in,
                              void* d_out, int out_size) {
    const float* x      = (const float*)d_in[0];
    const int*   ei     = (const int*)  d_in[1];
    const float* W1     = (const float*)d_in[2];
    const float* a1_src = (const float*)d_in[3];
    const float* a1_dst = (const float*)d_in[4];
    const float* W2     = (const float*)d_in[5];
    const float* a2_src = (const float*)d_in[6];
    const float* a2_dst = (const float*)d_in[7];

    int N = in_sizes[0] / DIM;
    int E = in_sizes[1] / 2;
    const int* src = ei;
    const int* dst = ei + E;

    float *hp, *ssrc, *sdst, *alpha, *inv;
    __nv_bfloat16 *ah, *al, *wh, *wl;
    int *cnt, *rowptr, *cursor, *srcs;
    cudaGetSymbolAddress((void**)&hp,     g_hp);
    cudaGetSymbolAddress((void**)&ah,     g_ah);
    cudaGetSymbolAddress((void**)&al,     g_al);
    cudaGetSymbolAddress((void**)&wh,     g_wh);
    cudaGetSymbolAddress((void**)&wl,     g_wl);
    cudaGetSymbolAddress((void**)&ssrc,   g_ssrc);
    cudaGetSymbolAddress((void**)&sdst,   g_sdst);
    cudaGetSymbolAddress((void**)&alpha,  g_alpha);
    cudaGetSymbolAddress((void**)&inv,    g_inv);
    cudaGetSymbolAddress((void**)&cnt,    g_cnt);
    cudaGetSymbolAddress((void**)&rowptr, g_rowptr);
    cudaGetSymbolAddress((void**)&cursor, g_cursor);
    cudaGetSymbolAddress((void**)&srcs,   g_srcs);

    float* out = (float*)d_out;
    __nv_bfloat16* wh2 = wh + DIM * DIM;
    __nv_bfloat16* wl2 = wl + DIM * DIM;

    static cudaStream_t s2 = nullptr;
    static cudaEvent_t ev_fork = nullptr, ev_csr = nullptr;
    if (!s2) {
        cudaStreamCreate(&s2);
        cudaEventCreateWithFlags(&ev_fork, cudaEventDisableTiming);
        cudaEventCreateWithFlags(&ev_csr, cudaEventDisableTiming);
    }

    cudaFuncSetAttribute(gemm_bf16<4>, cudaFuncAttributeMaxDynamicSharedMemorySize, SM_GEMM);
    cudaFuncSetAttribute(gemm_bf16<1>, cudaFuncAttributeMaxDynamicSharedMemorySize, SM_GEMM);

    dim3 gemm_grid((N + 127) / 128, 4);
    int n4x = N * DIM / 4;
    int n4w = DIM * DIM / 4;
    int nwarp_grid = (N * 32 + 255) / 256;

    // ---- fork: CSR build on side stream ----
    cudaEventRecord(ev_fork, 0);
    cudaStreamWaitEvent(s2, ev_fork, 0);
    cudaMemsetAsync(cnt, 0, (size_t)N * sizeof(int), s2);
    count_deg<<<(E + 255) / 256, 256, 0, s2>>>(dst, cnt, E);
    scan_rowptr<<<1, 1024, 0, s2>>>(cnt, rowptr, cursor, N);
    scatter_edges<<<(E + 255) / 256, 256, 0, s2>>>(src, dst, cursor, srcs, E);
    cudaEventRecord(ev_csr, s2);

    // ---- main stream: splits + zero scores + GEMM1 ----
    split_w2<<<(2 * n4w + 127) / 128, 128>>>(W1, W2, wh, wl, n4w);
    split_f4<<<(n4x + 127) / 128, 128>>>(x, ah, al, n4x);
    cudaMemsetAsync(ssrc, 0, (size_t)N * 4 * sizeof(float));
    cudaMemsetAsync(sdst, 0, (size_t)N * 4 * sizeof(float));
    gemm_bf16<4><<<gemm_grid, 256, SM_GEMM>>>(ah, al, wh, wl, hp, N,
                                              a1_src, a1_dst, ssrc, sdst);

    // ---- join CSR, layer-1 softmax + SpMM ----
    cudaStreamWaitEvent(0, ev_csr, 0);
    calc_alpha<4><<<nwarp_grid, 256>>>(rowptr, srcs, ssrc, sdst, alpha, inv, N);
    spmm_agg<4, true><<<N, 64>>>(rowptr, srcs, alpha, inv, hp, nullptr, ah, al);

    // ---- layer 2 (H=1) ----
    cudaMemsetAsync(ssrc, 0, (size_t)N * sizeof(float));
    cudaMemsetAsync(sdst, 0, (size_t)N * sizeof(float));
    gemm_bf16<1><<<gemm_grid, 256, SM_GEMM>>>(ah, al, wh2, wl2, hp, N,
                                              a2_src, a2_dst, ssrc, sdst);
    calc_alpha<1><<<nwarp_grid, 256>>>(rowptr, srcs, ssrc, sdst, alpha, inv, N);
    spmm_agg<1, false><<<N, 64>>>(rowptr, srcs, alpha, inv, hp, out, nullptr, nullptr);
}